// round 14
// baseline (speedup 1.0000x reference)
#include <cuda_runtime.h>
#include <cuda_bf16.h>
#include <math.h>
#include <stdint.h>

// Problem constants
#define B_   8
#define LQ_  1024
#define S_   256
#define D_   1024
#define H_   16
#define HD_  64
#define MQ_  (B_*LQ_)   // 8192
#define MKV_ (B_*S_)    // 2048
#define LDKV_ 2048      // merged K|V row stride

// ---------------------------------------------------------------------------
// Scratch (static device globals — no allocation in kernel_launch)
// ---------------------------------------------------------------------------
__device__ __nv_bfloat16 g_cAh[MQ_*D_],  g_cAl[MQ_*D_];    // concat(memory,gaze)
__device__ __nv_bfloat16 g_th [MKV_*D_], g_tl [MKV_*D_];   // text
__device__ __nv_bfloat16 g_wih[3*D_*D_], g_wil[3*D_*D_];   // w_in
__device__ __nv_bfloat16 g_woh[D_*D_],   g_wol[D_*D_];
__device__ __nv_bfloat16 g_w1h[D_*D_],   g_w1l[D_*D_];
__device__ __nv_bfloat16 g_w2h[D_*D_],   g_w2l[D_*D_];
__device__ __nv_bfloat16 g_qh [MQ_*D_],  g_ql [MQ_*D_];    // q (pre-scaled 1/8)
__device__ __nv_bfloat16 g_kvh[MKV_*LDKV_], g_kvl[MKV_*LDKV_]; // K|V merged
__device__ __nv_bfloat16 g_ch [MQ_*D_],  g_cl [MQ_*D_];    // ctx
__device__ __nv_bfloat16 g_ah [MQ_*D_],  g_al [MQ_*D_];    // attn_output
__device__ __nv_bfloat16 g_mh [MQ_*D_],  g_ml [MQ_*D_];    // relu mid
__device__ float g_att[MQ_*D_];                            // attn_output fp32
__device__ float g_ffn[MQ_*D_];                            // ffn fp32

// ---------------------------------------------------------------------------
// Baseline-ISA helpers (legal on plain compute_103)
// ---------------------------------------------------------------------------
__device__ __forceinline__ uint32_t smem_u32(const void* p) {
    uint32_t a;
    asm("{ .reg .u64 t; cvta.to.shared.u64 t, %1; cvt.u32.u64 %0, t; }"
        : "=r"(a) : "l"(p));
    return a;
}
__device__ __forceinline__ void ldsm_x4(uint32_t* r, uint32_t addr) {
    asm volatile("ldmatrix.sync.aligned.m8n8.x4.shared.b16 {%0,%1,%2,%3}, [%4];"
                 : "=r"(r[0]), "=r"(r[1]), "=r"(r[2]), "=r"(r[3]) : "r"(addr));
}
__device__ __forceinline__ void mma16816(float* d, const uint32_t* a,
                                         uint32_t b0, uint32_t b1) {
    asm volatile(
        "mma.sync.aligned.m16n8k16.row.col.f32.bf16.bf16.f32 "
        "{%0,%1,%2,%3}, {%4,%5,%6,%7}, {%8,%9}, {%0,%1,%2,%3};"
        : "+f"(d[0]), "+f"(d[1]), "+f"(d[2]), "+f"(d[3])
        : "r"(a[0]), "r"(a[1]), "r"(a[2]), "r"(a[3]), "r"(b0), "r"(b1));
}
__device__ __forceinline__ void cp16(uint32_t dst, const void* src) {
    asm volatile("cp.async.cg.shared.global [%0], [%1], 16;"
                 :: "r"(dst), "l"(src));
}
#define CP_COMMIT() asm volatile("cp.async.commit_group;" ::: "memory")
#define CP_WAIT0()  asm volatile("cp.async.wait_group 0;" ::: "memory")

// pack two fp32 into bf16x2 hi + residual-lo bf16x2 (lower half = first arg)
__device__ __forceinline__ void pack_hl(float x, float y,
                                        uint32_t& hi, uint32_t& lo) {
    asm("cvt.rn.bf16x2.f32 %0, %1, %2;" : "=r"(hi) : "f"(y), "f"(x));
    float rx = x - __uint_as_float(hi << 16);
    float ry = y - __uint_as_float(hi & 0xffff0000u);
    asm("cvt.rn.bf16x2.f32 %0, %1, %2;" : "=r"(lo) : "f"(ry), "f"(rx));
}

// ---------------------------------------------------------------------------
// One-time fp32 -> bf16 hi/lo splits
// ---------------------------------------------------------------------------
__global__ void cvt_split(const float* __restrict__ src, int sld,
                          __nv_bfloat16* __restrict__ hi,
                          __nv_bfloat16* __restrict__ lo,
                          int dld, int rows, int cols4)
{
    int idx = blockIdx.x * blockDim.x + threadIdx.x;
    if (idx >= rows * cols4) return;
    int row = idx / cols4, c = idx - row * cols4;
    float4 v = *(const float4*)(src + (size_t)row * sld + c * 4);
    uint32_t h01, h23, l01, l23;
    pack_hl(v.x, v.y, h01, l01);
    pack_hl(v.z, v.w, h23, l23);
    *(uint2*)(hi + (size_t)row * dld + c * 4) = make_uint2(h01, h23);
    *(uint2*)(lo + (size_t)row * dld + c * 4) = make_uint2(l01, l23);
}

// fused concat(memory, gaze) -> hi/lo  (rows MQ_, 256 cols4 of output)
__global__ void cvt_concat(const float* __restrict__ a, const float* __restrict__ b,
                           __nv_bfloat16* __restrict__ hi,
                           __nv_bfloat16* __restrict__ lo)
{
    int idx = blockIdx.x * blockDim.x + threadIdx.x;
    if (idx >= MQ_ * 256) return;
    int row = idx >> 8, c = idx & 255;
    const float* sp = (c < 128) ? a + (size_t)row * 512 + c * 4
                                : b + (size_t)row * 512 + (c - 128) * 4;
    float4 v = *(const float4*)sp;
    uint32_t h01, h23, l01, l23;
    pack_hl(v.x, v.y, h01, l01);
    pack_hl(v.z, v.w, h23, l23);
    *(uint2*)(hi + (size_t)row * D_ + c * 4) = make_uint2(h01, h23);
    *(uint2*)(lo + (size_t)row * D_ + c * 4) = make_uint2(l01, l23);
}

// three same-shape (D_ x D_) weights in one launch, selected by blockIdx.y
__global__ void cvt_split3(const float* __restrict__ s0, const float* __restrict__ s1,
                           const float* __restrict__ s2,
                           __nv_bfloat16* __restrict__ h0, __nv_bfloat16* __restrict__ l0,
                           __nv_bfloat16* __restrict__ h1, __nv_bfloat16* __restrict__ l1,
                           __nv_bfloat16* __restrict__ h2, __nv_bfloat16* __restrict__ l2)
{
    int idx = blockIdx.x * blockDim.x + threadIdx.x;
    if (idx >= D_ * 256) return;
    int which = blockIdx.y;
    const float* src = (which == 0) ? s0 : (which == 1) ? s1 : s2;
    __nv_bfloat16* hi = (which == 0) ? h0 : (which == 1) ? h1 : h2;
    __nv_bfloat16* lo = (which == 0) ? l0 : (which == 1) ? l1 : l2;
    int row = idx >> 8, c = idx & 255;
    float4 v = *(const float4*)(src + (size_t)row * D_ + c * 4);
    uint32_t h01, h23, l01, l23;
    pack_hl(v.x, v.y, h01, l01);
    pack_hl(v.z, v.w, h23, l23);
    *(uint2*)(hi + (size_t)row * D_ + c * 4) = make_uint2(h01, h23);
    *(uint2*)(lo + (size_t)row * D_ + c * 4) = make_uint2(l01, l23);
}

// ---------------------------------------------------------------------------
// gemm_bf3 v2: C = act(scale*((Ah+Al)(Bh+Bl)^T) + bias)... (bias pre-act)
// Tile 128x128, K-chunk 32, 80B padded rows (ldmatrix conflict-free, no XOR),
// 2-stage cp.async, 2 CTAs/SM. Term-major MMA order (dep distance 4).
// ---------------------------------------------------------------------------
#define G_ROW   80
#define G_TILE  (128 * G_ROW)           // 10240
#define G_STAGE (4 * G_TILE)            // 40960
#define G_DSMEM (2 * G_STAGE)           // 81920

__global__ __launch_bounds__(256, 2)
void gemm_bf3(int M, int N, int K,
              const __nv_bfloat16* __restrict__ Ah,
              const __nv_bfloat16* __restrict__ Al,
              const __nv_bfloat16* __restrict__ Bh,
              const __nv_bfloat16* __restrict__ Bl,
              const float* __restrict__ bias, float scale, int act,
              float* __restrict__ Cf,
              __nv_bfloat16* __restrict__ Ch, __nv_bfloat16* __restrict__ Cl,
              int ldc)
{
    extern __shared__ __align__(16) char smc[];
    const uint32_t sb = smem_u32(smc);
    const int tid = threadIdx.x, lane = tid & 31, w = tid >> 5;
    const int m0 = blockIdx.y * 128, n0 = blockIdx.x * 128;
    const int mrow = (w & 3) * 32, ncol = (w >> 2) * 64;

    float acc[2][8][4];
#pragma unroll
    for (int i = 0; i < 2; i++)
#pragma unroll
        for (int j = 0; j < 8; j++)
#pragma unroll
            for (int q = 0; q < 4; q++) acc[i][j][q] = 0.f;

    auto issue = [&](int c, int stage) {
        const int k0 = c * 32;
        const uint32_t st = sb + stage * G_STAGE;
#pragma unroll
        for (int it = 0; it < 2; it++) {
            int e = tid + it * 256;
            int r = e >> 2, cc = e & 3;
            uint32_t off = r * G_ROW + cc * 16;
            const size_t ga = (size_t)(m0 + r) * K + k0 + cc * 8;
            const size_t gb = (size_t)(n0 + r) * K + k0 + cc * 8;
            cp16(st + off,              Ah + ga);
            cp16(st + G_TILE + off,     Al + ga);
            cp16(st + 2 * G_TILE + off, Bh + gb);
            cp16(st + 3 * G_TILE + off, Bl + gb);
        }
    };

    const int NC = K / 32;
    issue(0, 0); CP_COMMIT();

    const int cadd = ((lane >> 4) & 1) * 16;
    for (int c = 0; c < NC; ++c) {
        CP_WAIT0();
        __syncthreads();        // all warps done reading the stage we refill
        if (c + 1 < NC) { issue(c + 1, (c + 1) & 1); CP_COMMIT(); }
        const uint32_t st = sb + (c & 1) * G_STAGE;
#pragma unroll
        for (int ks = 0; ks < 2; ks++) {
            const int kb = ks * 32 + cadd;
            uint32_t aH[2][4], aL[2][4];
#pragma unroll
            for (int mi = 0; mi < 2; mi++) {
                int rA = mrow + mi * 16 + (lane & 15);
                uint32_t off = rA * G_ROW + kb;
                ldsm_x4(aH[mi], st + off);
                ldsm_x4(aL[mi], st + G_TILE + off);
            }
#pragma unroll
            for (int j = 0; j < 4; j++) {
                int rB = ncol + j * 16 + (lane & 15);
                uint32_t off = rB * G_ROW + kb;
                uint32_t bh[4], bl[4];
                ldsm_x4(bh, st + 2 * G_TILE + off);
                ldsm_x4(bl, st + 3 * G_TILE + off);
                // term-major, mi-interleaved: dep distance 4 on each acc chain
                mma16816(acc[0][2*j],   aH[0], bh[0], bh[2]);
                mma16816(acc[1][2*j],   aH[1], bh[0], bh[2]);
                mma16816(acc[0][2*j+1], aH[0], bh[1], bh[3]);
                mma16816(acc[1][2*j+1], aH[1], bh[1], bh[3]);
                mma16816(acc[0][2*j],   aH[0], bl[0], bl[2]);
                mma16816(acc[1][2*j],   aH[1], bl[0], bl[2]);
                mma16816(acc[0][2*j+1], aH[0], bl[1], bl[3]);
                mma16816(acc[1][2*j+1], aH[1], bl[1], bl[3]);
                mma16816(acc[0][2*j],   aL[0], bh[0], bh[2]);
                mma16816(acc[1][2*j],   aL[1], bh[0], bh[2]);
                mma16816(acc[0][2*j+1], aL[0], bh[1], bh[3]);
                mma16816(acc[1][2*j+1], aL[1], bh[1], bh[3]);
            }
        }
        // no trailing sync: next iter's top barrier protects the stage swap
    }

    // epilogue: bias/relu/scale -> fp32 and/or bf16 hi/lo
    const int r0 = lane >> 2, c0 = (lane & 3) * 2;
#pragma unroll
    for (int mi = 0; mi < 2; mi++) {
#pragma unroll
        for (int ni = 0; ni < 8; ni++) {
            int gr = m0 + mrow + mi * 16 + r0;
            int gc = n0 + ncol + ni * 8 + c0;
            float b0v = bias[gc], b1v = bias[gc + 1];
            float v0 = acc[mi][ni][0] + b0v, v1 = acc[mi][ni][1] + b1v;
            float v2 = acc[mi][ni][2] + b0v, v3 = acc[mi][ni][3] + b1v;
            if (act) {
                v0 = fmaxf(v0, 0.f); v1 = fmaxf(v1, 0.f);
                v2 = fmaxf(v2, 0.f); v3 = fmaxf(v3, 0.f);
            }
            v0 *= scale; v1 *= scale; v2 *= scale; v3 *= scale;
            if (Cf) {
                *(float2*)&Cf[(size_t)gr * ldc + gc]       = make_float2(v0, v1);
                *(float2*)&Cf[(size_t)(gr + 8) * ldc + gc] = make_float2(v2, v3);
            }
            if (Ch) {
                uint32_t hh, ll;
                pack_hl(v0, v1, hh, ll);
                *(uint32_t*)&Ch[(size_t)gr * ldc + gc] = hh;
                *(uint32_t*)&Cl[(size_t)gr * ldc + gc] = ll;
                pack_hl(v2, v3, hh, ll);
                *(uint32_t*)&Ch[(size_t)(gr + 8) * ldc + gc] = hh;
                *(uint32_t*)&Cl[(size_t)(gr + 8) * ldc + gc] = ll;
            }
        }
    }
}

// ---------------------------------------------------------------------------
// HMMA flash attention (validated R13 core). K/V now read from merged KV
// buffer with row stride LDKV_ (K at col 0, V at col 1024).
// ---------------------------------------------------------------------------
#define AQH 0
#define AQL 16384
#define AKH 32768
#define AKL 65536
#define AVH 98304
#define AVL 131072
#define ATT_DSMEM 163840

__global__ __launch_bounds__(256, 1)
void attn_tc(const __nv_bfloat16* __restrict__ qh, const __nv_bfloat16* __restrict__ ql,
             const __nv_bfloat16* __restrict__ kvh, const __nv_bfloat16* __restrict__ kvl,
             __nv_bfloat16* __restrict__ ch, __nv_bfloat16* __restrict__ cl)
{
    extern __shared__ __align__(16) char smc[];
    const uint32_t sb = smem_u32(smc);
    const int tid = threadIdx.x, lane = tid & 31, w = tid >> 5;
    const int bq = blockIdx.x * 128;
    const int h  = blockIdx.y, b = blockIdx.z;

    // ---- loads (bf16 direct copies; V transposed) -------------------------
    const size_t qbase = ((size_t)(b * LQ_ + bq)) * D_ + h * HD_;
    for (int e = tid; e < 1024; e += 256) {
        int r = e >> 3, c = e & 7;
        uint32_t off = r * 128 + ((c * 16) ^ ((r & 7) << 4));
        *(uint4*)(smc + AQH + off) = *(const uint4*)(qh + qbase + (size_t)r * D_ + c * 8);
        *(uint4*)(smc + AQL + off) = *(const uint4*)(ql + qbase + (size_t)r * D_ + c * 8);
    }
    const size_t kbase = ((size_t)(b * S_)) * LDKV_ + h * HD_;
    for (int e = tid; e < 2048; e += 256) {
        int r = e >> 3, c = e & 7;
        uint32_t off = r * 128 + ((c * 16) ^ ((r & 7) << 4));
        *(uint4*)(smc + AKH + off) = *(const uint4*)(kvh + kbase + (size_t)r * LDKV_ + c * 8);
        *(uint4*)(smc + AKL + off) = *(const uint4*)(kvl + kbase + (size_t)r * LDKV_ + c * 8);
    }
    for (int e = tid; e < 2048; e += 256) {     // Vt[d][s], 512B rows
        int s = e >> 3, d8 = (e & 7) * 8;
        uint4 uh = *(const uint4*)(kvh + kbase + (size_t)s * LDKV_ + 1024 + d8);
        uint4 ul = *(const uint4*)(kvl + kbase + (size_t)s * LDKV_ + 1024 + d8);
        const __nv_bfloat16* ph = (const __nv_bfloat16*)&uh;
        const __nv_bfloat16* pl = (const __nv_bfloat16*)&ul;
#pragma unroll
        for (int t = 0; t < 8; t++) {
            int d = d8 + t;
            uint32_t off = d * 512 + ((s * 2) ^ ((d & 7) << 4));
            *(__nv_bfloat16*)(smc + AVH + off) = ph[t];
            *(__nv_bfloat16*)(smc + AVL + off) = pl[t];
        }
    }
    __syncthreads();

    // ---- per-warp flash loop ---------------------------------------------
    const int qr = w * 16;
    const int rA = qr + (lane & 15);
    const int cadd = ((lane >> 4) & 1) * 16;

    float O[8][4];
#pragma unroll
    for (int j = 0; j < 8; j++)
#pragma unroll
        for (int q = 0; q < 4; q++) O[j][q] = 0.f;
    float m0 = -1e30f, m1 = -1e30f, l0 = 0.f, l1 = 0.f;

    for (int t = 0; t < 4; ++t) {
        const int s0 = t * 64;
        float sc[8][4];
#pragma unroll
        for (int j = 0; j < 8; j++)
#pragma unroll
            for (int q = 0; q < 4; q++) sc[j][q] = 0.f;

        // scores = (Qh+Ql)(Kh+Kl)^T  (Q pre-scaled by 1/8)
#pragma unroll
        for (int ks = 0; ks < 4; ks++) {
            uint32_t qoff = rA * 128 + ((ks * 32 + cadd) ^ ((rA & 7) << 4));
            uint32_t aH[4], aL[4];
            ldsm_x4(aH, sb + AQH + qoff);
            ldsm_x4(aL, sb + AQL + qoff);
#pragma unroll
            for (int p = 0; p < 4; p++) {
                int rB = s0 + p * 16 + (lane & 15);
                uint32_t boff = rB * 128 + ((ks * 32 + cadd) ^ ((rB & 7) << 4));
                uint32_t bh[4], bl[4];
                ldsm_x4(bh, sb + AKH + boff);
                ldsm_x4(bl, sb + AKL + boff);
                mma16816(sc[2*p],   aH, bh[0], bh[2]);
                mma16816(sc[2*p+1], aH, bh[1], bh[3]);
                mma16816(sc[2*p],   aH, bl[0], bl[2]);
                mma16816(sc[2*p+1], aH, bl[1], bl[3]);
                mma16816(sc[2*p],   aL, bh[0], bh[2]);
                mma16816(sc[2*p+1], aL, bh[1], bh[3]);
            }
        }

        // online softmax (rows r0 = lane>>2 and r0+8; quad = lanes xor 1,2)
        float mx0 = -1e30f, mx1 = -1e30f;
#pragma unroll
        for (int j = 0; j < 8; j++) {
            mx0 = fmaxf(mx0, fmaxf(sc[j][0], sc[j][1]));
            mx1 = fmaxf(mx1, fmaxf(sc[j][2], sc[j][3]));
        }
        mx0 = fmaxf(mx0, __shfl_xor_sync(0xffffffffu, mx0, 1));
        mx0 = fmaxf(mx0, __shfl_xor_sync(0xffffffffu, mx0, 2));
        mx1 = fmaxf(mx1, __shfl_xor_sync(0xffffffffu, mx1, 1));
        mx1 = fmaxf(mx1, __shfl_xor_sync(0xffffffffu, mx1, 2));
        float mn0 = fmaxf(m0, mx0), mn1 = fmaxf(m1, mx1);
        float a0 = __expf(m0 - mn0), a1 = __expf(m1 - mn1);
        m0 = mn0; m1 = mn1;
        float ls0 = 0.f, ls1 = 0.f;
#pragma unroll
        for (int j = 0; j < 8; j++) {
            sc[j][0] = __expf(sc[j][0] - m0);
            sc[j][1] = __expf(sc[j][1] - m0);
            sc[j][2] = __expf(sc[j][2] - m1);
            sc[j][3] = __expf(sc[j][3] - m1);
            ls0 += sc[j][0] + sc[j][1];
            ls1 += sc[j][2] + sc[j][3];
        }
        ls0 += __shfl_xor_sync(0xffffffffu, ls0, 1);
        ls0 += __shfl_xor_sync(0xffffffffu, ls0, 2);
        ls1 += __shfl_xor_sync(0xffffffffu, ls1, 1);
        ls1 += __shfl_xor_sync(0xffffffffu, ls1, 2);
        l0 = l0 * a0 + ls0;
        l1 = l1 * a1 + ls1;
#pragma unroll
        for (int j = 0; j < 8; j++) {
            O[j][0] *= a0; O[j][1] *= a0;
            O[j][2] *= a1; O[j][3] *= a1;
        }

        // PV: O += (Ph+Pl)(Vth+Vtl)   (C-frag -> A-frag repack)
#pragma unroll
        for (int g = 0; g < 4; g++) {
            uint32_t aPh[4], aPl[4];
            pack_hl(sc[2*g][0],   sc[2*g][1],   aPh[0], aPl[0]);
            pack_hl(sc[2*g][2],   sc[2*g][3],   aPh[1], aPl[1]);
            pack_hl(sc[2*g+1][0], sc[2*g+1][1], aPh[2], aPl[2]);
            pack_hl(sc[2*g+1][2], sc[2*g+1][3], aPh[3], aPl[3]);
#pragma unroll
            for (int pd = 0; pd < 4; pd++) {
                int rV = pd * 16 + (lane & 15);
                uint32_t voff = rV * 512 +
                    (((s0 + g * 16) * 2 + cadd) ^ ((rV & 7) << 4));
                uint32_t bh[4], bl[4];
                ldsm_x4(bh, sb + AVH + voff);
                ldsm_x4(bl, sb + AVL + voff);
                mma16816(O[2*pd],   aPh, bh[0], bh[2]);
                mma16816(O[2*pd+1], aPh, bh[1], bh[3]);
                mma16816(O[2*pd],   aPh, bl[0], bl[2]);
                mma16816(O[2*pd+1], aPh, bl[1], bl[3]);
                mma16816(O[2*pd],   aPl, bh[0], bh[2]);
                mma16816(O[2*pd+1], aPl, bh[1], bh[3]);
            }
        }
    }

    // ---- epilogue: O/l -> ctx bf16 hi/lo ---------------------------------
    const float i0 = 1.f / l0, i1 = 1.f / l1;
    const size_t gr0 = (size_t)(b * LQ_ + bq + qr + (lane >> 2));
    const size_t gr1 = gr0 + 8;
#pragma unroll
    for (int j = 0; j < 8; j++) {
        int gc = h * HD_ + j * 8 + (lane & 3) * 2;
        uint32_t hh, ll;
        pack_hl(O[j][0] * i0, O[j][1] * i0, hh, ll);
        *(uint32_t*)&ch[gr0 * D_ + gc] = hh;
        *(uint32_t*)&cl[gr0 * D_ + gc] = ll;
        pack_hl(O[j][2] * i1, O[j][3] * i1, hh, ll);
        *(uint32_t*)&ch[gr1 * D_ + gc] = hh;
        *(uint32_t*)&cl[gr1 * D_ + gc] = ll;
    }
}

// ---------------------------------------------------------------------------
// Epilogue: two layer-norms + sigmoid box (unchanged)
// ---------------------------------------------------------------------------
#define OUT_TGT 8388608u
#define OUT_BOX 16777216u

__global__ __launch_bounds__(256)
void ln_box_kernel(const float* __restrict__ ffn, const float* __restrict__ attn,
                   const float* __restrict__ g1, const float* __restrict__ be1,
                   const float* __restrict__ g2, const float* __restrict__ be2,
                   float* __restrict__ out)
{
    __shared__ float red[8];
    __shared__ float bcast;
    const int row = blockIdx.x;
    const int tid = threadIdx.x;
    const int lane = tid & 31, w = tid >> 5;

    float4 x = ((const float4*)(ffn + (size_t)row * D_))[tid];

    float s = x.x + x.y + x.z + x.w;
#pragma unroll
    for (int o = 16; o; o >>= 1) s += __shfl_xor_sync(0xffffffffu, s, o);
    if (lane == 0) red[w] = s;
    __syncthreads();
    if (w == 0) {
        float t = (lane < 8) ? red[lane] : 0.f;
#pragma unroll
        for (int o = 4; o; o >>= 1) t += __shfl_xor_sync(0xffffffffu, t, o);
        if (lane == 0) bcast = t * (1.f / 1024.f);
    }
    __syncthreads();
    const float mean = bcast;
    __syncthreads();

    float dx = x.x - mean, dy = x.y - mean, dz = x.z - mean, dw = x.w - mean;
    float sq = dx * dx + dy * dy + dz * dz + dw * dw;
#pragma unroll
    for (int o = 16; o; o >>= 1) sq += __shfl_xor_sync(0xffffffffu, sq, o);
    if (lane == 0) red[w] = sq;
    __syncthreads();
    if (w == 0) {
        float t = (lane < 8) ? red[lane] : 0.f;
#pragma unroll
        for (int o = 4; o; o >>= 1) t += __shfl_xor_sync(0xffffffffu, t, o);
        if (lane == 0) bcast = rsqrtf(t * (1.f / 1024.f) + 1e-5f);
    }
    __syncthreads();
    const float inv = bcast;

    float4 G1 = ((const float4*)g1)[tid];
    float4 B1 = ((const float4*)be1)[tid];
    float4 G2 = ((const float4*)g2)[tid];
    float4 B2 = ((const float4*)be2)[tid];

    float4 o1, o2;
    o1.x = dx * inv * G1.x + B1.x;  o2.x = dx * inv * G2.x + B2.x;
    o1.y = dy * inv * G1.y + B1.y;  o2.y = dy * inv * G2.y + B2.y;
    o1.z = dz * inv * G1.z + B1.z;  o2.z = dz * inv * G2.z + B2.z;
    o1.w = dw * inv * G1.w + B1.w;  o2.w = dw * inv * G2.w + B2.w;

    ((float4*)out)[(size_t)row * 256 + tid]             = o1;
    ((float4*)(out + OUT_TGT))[(size_t)row * 256 + tid] = o2;

    if (tid == 0) {
        const float* a = attn + (size_t)row * D_;
        float xc = 1.f / (1.f + __expf(-a[0]));
        float yc = 1.f / (1.f + __expf(-a[1]));
        float ww = 1.f / (1.f + __expf(-a[2]));
        float hh = 1.f / (1.f + __expf(-a[3]));
        float4 box = make_float4(xc - ww * 0.5f, yc - hh * 0.5f,
                                 xc + ww * 0.5f, yc + hh * 0.5f);
        *(float4*)(out + OUT_BOX + (size_t)row * 4) = box;
    }
}

// ---------------------------------------------------------------------------
// Launch
// ---------------------------------------------------------------------------
extern "C" void kernel_launch(void* const* d_in, const int* in_sizes, int n_in,
                              void* d_out, int out_size)
{
    const float* memory = (const float*)d_in[0];
    const float* gaze   = (const float*)d_in[1];
    const float* text   = (const float*)d_in[2];
    const float* w_in   = (const float*)d_in[3];
    const float* b_in   = (const float*)d_in[4];
    const float* w_o    = (const float*)d_in[5];
    const float* b_o    = (const float*)d_in[6];
    const float* w1     = (const float*)d_in[7];
    const float* b1     = (const float*)d_in[8];
    const float* w2     = (const float*)d_in[9];
    const float* b2     = (const float*)d_in[10];
    const float* g1     = (const float*)d_in[11];
    const float* be1    = (const float*)d_in[12];
    const float* g2     = (const float*)d_in[13];
    const float* be2    = (const float*)d_in[14];
    float* out = (float*)d_out;

    __nv_bfloat16 *cAh,*cAl,*th,*tl,*wih,*wil,*woh,*wol,*w1h,*w1l,*w2h,*w2l;
    __nv_bfloat16 *qh,*ql,*kvh,*kvl,*chb,*clb,*ah,*al,*mh,*ml;
    float *ATT,*FFN;
    cudaGetSymbolAddress((void**)&cAh, g_cAh); cudaGetSymbolAddress((void**)&cAl, g_cAl);
    cudaGetSymbolAddress((void**)&th,  g_th);  cudaGetSymbolAddress((void**)&tl,  g_tl);
    cudaGetSymbolAddress((void**)&wih, g_wih); cudaGetSymbolAddress((void**)&wil, g_wil);
    cudaGetSymbolAddress((void**)&woh, g_woh); cudaGetSymbolAddress((void**)&wol, g_wol);
    cudaGetSymbolAddress((void**)&w1h, g_w1h); cudaGetSymbolAddress((void**)&w1l, g_w1l);
    cudaGetSymbolAddress((void**)&w2h, g_w2h); cudaGetSymbolAddress((void**)&w2l, g_w2l);
    cudaGetSymbolAddress((void**)&qh,  g_qh);  cudaGetSymbolAddress((void**)&ql,  g_ql);
    cudaGetSymbolAddress((void**)&kvh, g_kvh); cudaGetSymbolAddress((void**)&kvl, g_kvl);
    cudaGetSymbolAddress((void**)&chb, g_ch);  cudaGetSymbolAddress((void**)&clb, g_cl);
    cudaGetSymbolAddress((void**)&ah,  g_ah);  cudaGetSymbolAddress((void**)&al,  g_al);
    cudaGetSymbolAddress((void**)&mh,  g_mh);  cudaGetSymbolAddress((void**)&ml,  g_ml);
    cudaGetSymbolAddress((void**)&ATT, g_att); cudaGetSymbolAddress((void**)&FFN, g_ffn);

    cudaFuncSetAttribute(gemm_bf3,
                         cudaFuncAttributeMaxDynamicSharedMemorySize, G_DSMEM);
    cudaFuncSetAttribute(attn_tc,
                         cudaFuncAttributeMaxDynamicSharedMemorySize, ATT_DSMEM);

    dim3 blk(256);

    // ---- one-time input/weight splits (4 launches) ----
    cvt_concat<<<(MQ_ * 256 + 255) / 256, blk>>>(memory, gaze, cAh, cAl);
    cvt_split <<<(MKV_ * 256 + 255) / 256, blk>>>(text, 1024, th, tl, 1024, MKV_, 256);
    cvt_split <<<(3 * D_ * 256 + 255) / 256, blk>>>(w_in, 1024, wih, wil, 1024, 3 * D_, 256);
    {
        dim3 g3((D_ * 256 + 255) / 256, 3);
        cvt_split3<<<g3, blk>>>(w_o, w1, w2, woh, wol, w1h, w1l, w2h, w2l);
    }

    dim3 gQ(D_ / 128, MQ_ / 128);     // (8, 64)
    dim3 gKV(LDKV_ / 128, MKV_ / 128);// (16, 16) merged K|V

    // Q projection (scale 1/8 folded in), bf16 out only
    gemm_bf3<<<gQ, blk, G_DSMEM>>>(MQ_, D_, D_, cAh, cAl, wih, wil,
                                   b_in, 0.125f, 0, nullptr, qh, ql, D_);
    // merged K|V projection: B rows = w_in[D..3D), bias b_in[D..3D)
    gemm_bf3<<<gKV, blk, G_DSMEM>>>(MKV_, LDKV_, D_, th, tl,
                                    wih + (size_t)D_ * D_, wil + (size_t)D_ * D_,
                                    b_in + D_, 1.f, 0, nullptr, kvh, kvl, LDKV_);
    // attention -> ctx bf16 hi/lo
    dim3 gA(LQ_ / 128, H_, B_);       // (8, 16, 8)
    attn_tc<<<gA, blk, ATT_DSMEM>>>(qh, ql, kvh, kvl, chb, clb);
    // output projection -> ATT fp32 + bf16
    gemm_bf3<<<gQ, blk, G_DSMEM>>>(MQ_, D_, D_, chb, clb, woh, wol,
                                   b_o, 1.f, 0, ATT, ah, al, D_);
    // FFN1 (relu) -> bf16 only
    gemm_bf3<<<gQ, blk, G_DSMEM>>>(MQ_, D_, D_, ah, al, w1h, w1l,
                                   b1, 1.f, 1, nullptr, mh, ml, D_);
    // FFN2 -> fp32 only
    gemm_bf3<<<gQ, blk, G_DSMEM>>>(MQ_, D_, D_, mh, ml, w2h, w2l,
                                   b2, 1.f, 0, FFN, nullptr, nullptr, D_);

    // layer norms + box proposal
    ln_box_kernel<<<MQ_, blk>>>(FFN, ATT, g1, be1, g2, be2, out);
}

// round 15
// speedup vs baseline: 1.1230x; 1.1230x over previous
#include <cuda_runtime.h>
#include <cuda_bf16.h>
#include <math.h>
#include <stdint.h>

// Problem constants
#define B_   8
#define LQ_  1024
#define S_   256
#define D_   1024
#define H_   16
#define HD_  64
#define MQ_  (B_*LQ_)   // 8192
#define MKV_ (B_*S_)    // 2048
#define LDKV_ 2048      // merged K|V row stride

// ---------------------------------------------------------------------------
// Scratch (static device globals — no allocation in kernel_launch)
// ---------------------------------------------------------------------------
__device__ __nv_bfloat16 g_cAh[MQ_*D_],  g_cAl[MQ_*D_];    // concat(memory,gaze)
__device__ __nv_bfloat16 g_th [MKV_*D_], g_tl [MKV_*D_];   // text
__device__ __nv_bfloat16 g_wih[3*D_*D_], g_wil[3*D_*D_];   // w_in
__device__ __nv_bfloat16 g_woh[D_*D_],   g_wol[D_*D_];
__device__ __nv_bfloat16 g_w1h[D_*D_],   g_w1l[D_*D_];
__device__ __nv_bfloat16 g_w2h[D_*D_],   g_w2l[D_*D_];
__device__ __nv_bfloat16 g_qh [MQ_*D_],  g_ql [MQ_*D_];    // q (pre-scaled 1/8)
__device__ __nv_bfloat16 g_kvh[MKV_*LDKV_], g_kvl[MKV_*LDKV_]; // K|V merged
__device__ __nv_bfloat16 g_ch [MQ_*D_],  g_cl [MQ_*D_];    // ctx
__device__ __nv_bfloat16 g_ah [MQ_*D_],  g_al [MQ_*D_];    // attn_output
__device__ __nv_bfloat16 g_mh [MQ_*D_],  g_ml [MQ_*D_];    // relu mid
__device__ float g_att[MQ_*D_];                            // attn_output fp32
__device__ float g_ffn[MQ_*D_];                            // ffn fp32

// ---------------------------------------------------------------------------
// Baseline-ISA helpers (legal on plain compute_103)
// ---------------------------------------------------------------------------
__device__ __forceinline__ uint32_t smem_u32(const void* p) {
    uint32_t a;
    asm("{ .reg .u64 t; cvta.to.shared.u64 t, %1; cvt.u32.u64 %0, t; }"
        : "=r"(a) : "l"(p));
    return a;
}
__device__ __forceinline__ void ldsm_x4(uint32_t* r, uint32_t addr) {
    asm volatile("ldmatrix.sync.aligned.m8n8.x4.shared.b16 {%0,%1,%2,%3}, [%4];"
                 : "=r"(r[0]), "=r"(r[1]), "=r"(r[2]), "=r"(r[3]) : "r"(addr));
}
__device__ __forceinline__ void mma16816(float* d, const uint32_t* a,
                                         uint32_t b0, uint32_t b1) {
    asm volatile(
        "mma.sync.aligned.m16n8k16.row.col.f32.bf16.bf16.f32 "
        "{%0,%1,%2,%3}, {%4,%5,%6,%7}, {%8,%9}, {%0,%1,%2,%3};"
        : "+f"(d[0]), "+f"(d[1]), "+f"(d[2]), "+f"(d[3])
        : "r"(a[0]), "r"(a[1]), "r"(a[2]), "r"(a[3]), "r"(b0), "r"(b1));
}
__device__ __forceinline__ void cp16(uint32_t dst, const void* src) {
    asm volatile("cp.async.cg.shared.global [%0], [%1], 16;"
                 :: "r"(dst), "l"(src));
}
#define CP_COMMIT() asm volatile("cp.async.commit_group;" ::: "memory")
#define CP_WAIT0()  asm volatile("cp.async.wait_group 0;" ::: "memory")

// pack two fp32 into bf16x2 hi + residual-lo bf16x2 (lower half = first arg)
__device__ __forceinline__ void pack_hl(float x, float y,
                                        uint32_t& hi, uint32_t& lo) {
    asm("cvt.rn.bf16x2.f32 %0, %1, %2;" : "=r"(hi) : "f"(y), "f"(x));
    float rx = x - __uint_as_float(hi << 16);
    float ry = y - __uint_as_float(hi & 0xffff0000u);
    asm("cvt.rn.bf16x2.f32 %0, %1, %2;" : "=r"(lo) : "f"(ry), "f"(rx));
}

// ---------------------------------------------------------------------------
// One-time fp32 -> bf16 hi/lo splits
// ---------------------------------------------------------------------------
__global__ void cvt_split(const float* __restrict__ src, int sld,
                          __nv_bfloat16* __restrict__ hi,
                          __nv_bfloat16* __restrict__ lo,
                          int dld, int rows, int cols4)
{
    int idx = blockIdx.x * blockDim.x + threadIdx.x;
    if (idx >= rows * cols4) return;
    int row = idx / cols4, c = idx - row * cols4;
    float4 v = *(const float4*)(src + (size_t)row * sld + c * 4);
    uint32_t h01, h23, l01, l23;
    pack_hl(v.x, v.y, h01, l01);
    pack_hl(v.z, v.w, h23, l23);
    *(uint2*)(hi + (size_t)row * dld + c * 4) = make_uint2(h01, h23);
    *(uint2*)(lo + (size_t)row * dld + c * 4) = make_uint2(l01, l23);
}

// fused concat(memory, gaze) -> hi/lo  (rows MQ_, 256 cols4 of output)
__global__ void cvt_concat(const float* __restrict__ a, const float* __restrict__ b,
                           __nv_bfloat16* __restrict__ hi,
                           __nv_bfloat16* __restrict__ lo)
{
    int idx = blockIdx.x * blockDim.x + threadIdx.x;
    if (idx >= MQ_ * 256) return;
    int row = idx >> 8, c = idx & 255;
    const float* sp = (c < 128) ? a + (size_t)row * 512 + c * 4
                                : b + (size_t)row * 512 + (c - 128) * 4;
    float4 v = *(const float4*)sp;
    uint32_t h01, h23, l01, l23;
    pack_hl(v.x, v.y, h01, l01);
    pack_hl(v.z, v.w, h23, l23);
    *(uint2*)(hi + (size_t)row * D_ + c * 4) = make_uint2(h01, h23);
    *(uint2*)(lo + (size_t)row * D_ + c * 4) = make_uint2(l01, l23);
}

// three same-shape (D_ x D_) weights in one launch, selected by blockIdx.y
__global__ void cvt_split3(const float* __restrict__ s0, const float* __restrict__ s1,
                           const float* __restrict__ s2,
                           __nv_bfloat16* __restrict__ h0, __nv_bfloat16* __restrict__ l0,
                           __nv_bfloat16* __restrict__ h1, __nv_bfloat16* __restrict__ l1,
                           __nv_bfloat16* __restrict__ h2, __nv_bfloat16* __restrict__ l2)
{
    int idx = blockIdx.x * blockDim.x + threadIdx.x;
    if (idx >= D_ * 256) return;
    int which = blockIdx.y;
    const float* src = (which == 0) ? s0 : (which == 1) ? s1 : s2;
    __nv_bfloat16* hi = (which == 0) ? h0 : (which == 1) ? h1 : h2;
    __nv_bfloat16* lo = (which == 0) ? l0 : (which == 1) ? l1 : l2;
    int row = idx >> 8, c = idx & 255;
    float4 v = *(const float4*)(src + (size_t)row * D_ + c * 4);
    uint32_t h01, h23, l01, l23;
    pack_hl(v.x, v.y, h01, l01);
    pack_hl(v.z, v.w, h23, l23);
    *(uint2*)(hi + (size_t)row * D_ + c * 4) = make_uint2(h01, h23);
    *(uint2*)(lo + (size_t)row * D_ + c * 4) = make_uint2(l01, l23);
}

// ---------------------------------------------------------------------------
// gemm_bf3 (R13 core, 256x128 tile): C = act((Ah+Al)(Bh+Bl)^T + bias)*scale
// 512 threads, 16 warps (warp = 32x64), K-chunk 64, XOR-swizzled 128B rows,
// 2-stage cp.async double buffer (2 x 96KB).
// ---------------------------------------------------------------------------
#define GA_TILE 32768                   // A hi (256 x 64 bf16)
#define GB_TILE 16384                   // B hi (128 x 64 bf16)
#define G_STAGE (2 * GA_TILE + 2 * GB_TILE)   // 98304
#define G_DSMEM (2 * G_STAGE)                 // 196608

__global__ __launch_bounds__(512, 1)
void gemm_bf3(int M, int N, int K,
              const __nv_bfloat16* __restrict__ Ah,
              const __nv_bfloat16* __restrict__ Al,
              const __nv_bfloat16* __restrict__ Bh,
              const __nv_bfloat16* __restrict__ Bl,
              const float* __restrict__ bias, float scale, int act,
              float* __restrict__ Cf,
              __nv_bfloat16* __restrict__ Ch, __nv_bfloat16* __restrict__ Cl,
              int ldc)
{
    extern __shared__ __align__(16) char smc[];
    const uint32_t sb = smem_u32(smc);
    const int tid = threadIdx.x, lane = tid & 31, w = tid >> 5;
    const int m0 = blockIdx.y * 256, n0 = blockIdx.x * 128;
    const int mrow = (w & 7) * 32, ncol = (w >> 3) * 64;

    float acc[2][8][4];
#pragma unroll
    for (int i = 0; i < 2; i++)
#pragma unroll
        for (int j = 0; j < 8; j++)
#pragma unroll
            for (int q = 0; q < 4; q++) acc[i][j][q] = 0.f;

    auto issue = [&](int c, int stage) {
        const int k0 = c * 64;
        const uint32_t st = sb + stage * G_STAGE;
        // A: 256 rows x 64 bf16 (hi+lo)
#pragma unroll
        for (int it = 0; it < 4; it++) {
            int e = tid + it * 512;
            int r = e >> 3, cc = e & 7;
            uint32_t off = r * 128 + ((cc * 16) ^ ((r & 7) << 4));
            const size_t ga = (size_t)(m0 + r) * K + k0 + cc * 8;
            cp16(st + off,           Ah + ga);
            cp16(st + GA_TILE + off, Al + ga);
        }
        // B: 128 rows x 64 bf16 (hi+lo)
#pragma unroll
        for (int it = 0; it < 2; it++) {
            int e = tid + it * 512;
            int r = e >> 3, cc = e & 7;
            uint32_t off = r * 128 + ((cc * 16) ^ ((r & 7) << 4));
            const size_t gb = (size_t)(n0 + r) * K + k0 + cc * 8;
            cp16(st + 2 * GA_TILE + off,           Bh + gb);
            cp16(st + 2 * GA_TILE + GB_TILE + off, Bl + gb);
        }
    };

    const int NC = K / 64;
    issue(0, 0); CP_COMMIT();

    const int cadd = ((lane >> 4) & 1) * 16;
    for (int c = 0; c < NC; ++c) {
        CP_WAIT0();
        __syncthreads();
        if (c + 1 < NC) { issue(c + 1, (c + 1) & 1); CP_COMMIT(); }
        const uint32_t st = sb + (c & 1) * G_STAGE;
#pragma unroll
        for (int ks = 0; ks < 4; ks++) {
            uint32_t aH[2][4], aL[2][4];
#pragma unroll
            for (int mi = 0; mi < 2; mi++) {
                int rA = mrow + mi * 16 + (lane & 15);
                uint32_t off = rA * 128 + ((ks * 32 + cadd) ^ ((rA & 7) << 4));
                ldsm_x4(aH[mi], st + off);
                ldsm_x4(aL[mi], st + GA_TILE + off);
            }
#pragma unroll
            for (int j = 0; j < 4; j++) {
                int rB = ncol + j * 16 + (lane & 15);
                uint32_t off = rB * 128 + ((ks * 32 + cadd) ^ ((rB & 7) << 4));
                uint32_t bh[4], bl[4];
                ldsm_x4(bh, st + 2 * GA_TILE + off);
                ldsm_x4(bl, st + 2 * GA_TILE + GB_TILE + off);
#pragma unroll
                for (int mi = 0; mi < 2; mi++) {
                    mma16816(acc[mi][2*j],   aH[mi], bh[0], bh[2]);
                    mma16816(acc[mi][2*j+1], aH[mi], bh[1], bh[3]);
                    mma16816(acc[mi][2*j],   aH[mi], bl[0], bl[2]);
                    mma16816(acc[mi][2*j+1], aH[mi], bl[1], bl[3]);
                    mma16816(acc[mi][2*j],   aL[mi], bh[0], bh[2]);
                    mma16816(acc[mi][2*j+1], aL[mi], bh[1], bh[3]);
                }
            }
        }
        __syncthreads();
    }

    // epilogue: bias/relu/scale -> fp32 and/or bf16 hi/lo
    const int r0 = lane >> 2, c0 = (lane & 3) * 2;
#pragma unroll
    for (int mi = 0; mi < 2; mi++) {
#pragma unroll
        for (int ni = 0; ni < 8; ni++) {
            int gr = m0 + mrow + mi * 16 + r0;
            int gc = n0 + ncol + ni * 8 + c0;
            float b0v = bias[gc], b1v = bias[gc + 1];
            float v0 = acc[mi][ni][0] + b0v, v1 = acc[mi][ni][1] + b1v;
            float v2 = acc[mi][ni][2] + b0v, v3 = acc[mi][ni][3] + b1v;
            if (act) {
                v0 = fmaxf(v0, 0.f); v1 = fmaxf(v1, 0.f);
                v2 = fmaxf(v2, 0.f); v3 = fmaxf(v3, 0.f);
            }
            v0 *= scale; v1 *= scale; v2 *= scale; v3 *= scale;
            if (Cf) {
                *(float2*)&Cf[(size_t)gr * ldc + gc]       = make_float2(v0, v1);
                *(float2*)&Cf[(size_t)(gr + 8) * ldc + gc] = make_float2(v2, v3);
            }
            if (Ch) {
                uint32_t hh, ll;
                pack_hl(v0, v1, hh, ll);
                *(uint32_t*)&Ch[(size_t)gr * ldc + gc] = hh;
                *(uint32_t*)&Cl[(size_t)gr * ldc + gc] = ll;
                pack_hl(v2, v3, hh, ll);
                *(uint32_t*)&Ch[(size_t)(gr + 8) * ldc + gc] = hh;
                *(uint32_t*)&Cl[(size_t)(gr + 8) * ldc + gc] = ll;
            }
        }
    }
}

// ---------------------------------------------------------------------------
// HMMA flash attention (validated R13/R14 core; merged-KV inputs).
// ---------------------------------------------------------------------------
#define AQH 0
#define AQL 16384
#define AKH 32768
#define AKL 65536
#define AVH 98304
#define AVL 131072
#define ATT_DSMEM 163840

__global__ __launch_bounds__(256, 1)
void attn_tc(const __nv_bfloat16* __restrict__ qh, const __nv_bfloat16* __restrict__ ql,
             const __nv_bfloat16* __restrict__ kvh, const __nv_bfloat16* __restrict__ kvl,
             __nv_bfloat16* __restrict__ ch, __nv_bfloat16* __restrict__ cl)
{
    extern __shared__ __align__(16) char smc[];
    const uint32_t sb = smem_u32(smc);
    const int tid = threadIdx.x, lane = tid & 31, w = tid >> 5;
    const int bq = blockIdx.x * 128;
    const int h  = blockIdx.y, b = blockIdx.z;

    // ---- loads (bf16 direct copies; V transposed) -------------------------
    const size_t qbase = ((size_t)(b * LQ_ + bq)) * D_ + h * HD_;
    for (int e = tid; e < 1024; e += 256) {
        int r = e >> 3, c = e & 7;
        uint32_t off = r * 128 + ((c * 16) ^ ((r & 7) << 4));
        *(uint4*)(smc + AQH + off) = *(const uint4*)(qh + qbase + (size_t)r * D_ + c * 8);
        *(uint4*)(smc + AQL + off) = *(const uint4*)(ql + qbase + (size_t)r * D_ + c * 8);
    }
    const size_t kbase = ((size_t)(b * S_)) * LDKV_ + h * HD_;
    for (int e = tid; e < 2048; e += 256) {
        int r = e >> 3, c = e & 7;
        uint32_t off = r * 128 + ((c * 16) ^ ((r & 7) << 4));
        *(uint4*)(smc + AKH + off) = *(const uint4*)(kvh + kbase + (size_t)r * LDKV_ + c * 8);
        *(uint4*)(smc + AKL + off) = *(const uint4*)(kvl + kbase + (size_t)r * LDKV_ + c * 8);
    }
    for (int e = tid; e < 2048; e += 256) {     // Vt[d][s], 512B rows
        int s = e >> 3, d8 = (e & 7) * 8;
        uint4 uh = *(const uint4*)(kvh + kbase + (size_t)s * LDKV_ + 1024 + d8);
        uint4 ul = *(const uint4*)(kvl + kbase + (size_t)s * LDKV_ + 1024 + d8);
        const __nv_bfloat16* ph = (const __nv_bfloat16*)&uh;
        const __nv_bfloat16* pl = (const __nv_bfloat16*)&ul;
#pragma unroll
        for (int t = 0; t < 8; t++) {
            int d = d8 + t;
            uint32_t off = d * 512 + ((s * 2) ^ ((d & 7) << 4));
            *(__nv_bfloat16*)(smc + AVH + off) = ph[t];
            *(__nv_bfloat16*)(smc + AVL + off) = pl[t];
        }
    }
    __syncthreads();

    // ---- per-warp flash loop ---------------------------------------------
    const int qr = w * 16;
    const int rA = qr + (lane & 15);
    const int cadd = ((lane >> 4) & 1) * 16;

    float O[8][4];
#pragma unroll
    for (int j = 0; j < 8; j++)
#pragma unroll
        for (int q = 0; q < 4; q++) O[j][q] = 0.f;
    float m0 = -1e30f, m1 = -1e30f, l0 = 0.f, l1 = 0.f;

    for (int t = 0; t < 4; ++t) {
        const int s0 = t * 64;
        float sc[8][4];
#pragma unroll
        for (int j = 0; j < 8; j++)
#pragma unroll
            for (int q = 0; q < 4; q++) sc[j][q] = 0.f;

        // scores = (Qh+Ql)(Kh+Kl)^T  (Q pre-scaled by 1/8)
#pragma unroll
        for (int ks = 0; ks < 4; ks++) {
            uint32_t qoff = rA * 128 + ((ks * 32 + cadd) ^ ((rA & 7) << 4));
            uint32_t aH[4], aL[4];
            ldsm_x4(aH, sb + AQH + qoff);
            ldsm_x4(aL, sb + AQL + qoff);
#pragma unroll
            for (int p = 0; p < 4; p++) {
                int rB = s0 + p * 16 + (lane & 15);
                uint32_t boff = rB * 128 + ((ks * 32 + cadd) ^ ((rB & 7) << 4));
                uint32_t bh[4], bl[4];
                ldsm_x4(bh, sb + AKH + boff);
                ldsm_x4(bl, sb + AKL + boff);
                mma16816(sc[2*p],   aH, bh[0], bh[2]);
                mma16816(sc[2*p+1], aH, bh[1], bh[3]);
                mma16816(sc[2*p],   aH, bl[0], bl[2]);
                mma16816(sc[2*p+1], aH, bl[1], bl[3]);
                mma16816(sc[2*p],   aL, bh[0], bh[2]);
                mma16816(sc[2*p+1], aL, bh[1], bh[3]);
            }
        }

        // online softmax (rows r0 = lane>>2 and r0+8; quad = lanes xor 1,2)
        float mx0 = -1e30f, mx1 = -1e30f;
#pragma unroll
        for (int j = 0; j < 8; j++) {
            mx0 = fmaxf(mx0, fmaxf(sc[j][0], sc[j][1]));
            mx1 = fmaxf(mx1, fmaxf(sc[j][2], sc[j][3]));
        }
        mx0 = fmaxf(mx0, __shfl_xor_sync(0xffffffffu, mx0, 1));
        mx0 = fmaxf(mx0, __shfl_xor_sync(0xffffffffu, mx0, 2));
        mx1 = fmaxf(mx1, __shfl_xor_sync(0xffffffffu, mx1, 1));
        mx1 = fmaxf(mx1, __shfl_xor_sync(0xffffffffu, mx1, 2));
        float mn0 = fmaxf(m0, mx0), mn1 = fmaxf(m1, mx1);
        float a0 = __expf(m0 - mn0), a1 = __expf(m1 - mn1);
        m0 = mn0; m1 = mn1;
        float ls0 = 0.f, ls1 = 0.f;
#pragma unroll
        for (int j = 0; j < 8; j++) {
            sc[j][0] = __expf(sc[j][0] - m0);
            sc[j][1] = __expf(sc[j][1] - m0);
            sc[j][2] = __expf(sc[j][2] - m1);
            sc[j][3] = __expf(sc[j][3] - m1);
            ls0 += sc[j][0] + sc[j][1];
            ls1 += sc[j][2] + sc[j][3];
        }
        ls0 += __shfl_xor_sync(0xffffffffu, ls0, 1);
        ls0 += __shfl_xor_sync(0xffffffffu, ls0, 2);
        ls1 += __shfl_xor_sync(0xffffffffu, ls1, 1);
        ls1 += __shfl_xor_sync(0xffffffffu, ls1, 2);
        l0 = l0 * a0 + ls0;
        l1 = l1 * a1 + ls1;
#pragma unroll
        for (int j = 0; j < 8; j++) {
            O[j][0] *= a0; O[j][1] *= a0;
            O[j][2] *= a1; O[j][3] *= a1;
        }

        // PV: O += (Ph+Pl)(Vth+Vtl)   (C-frag -> A-frag repack)
#pragma unroll
        for (int g = 0; g < 4; g++) {
            uint32_t aPh[4], aPl[4];
            pack_hl(sc[2*g][0],   sc[2*g][1],   aPh[0], aPl[0]);
            pack_hl(sc[2*g][2],   sc[2*g][3],   aPh[1], aPl[1]);
            pack_hl(sc[2*g+1][0], sc[2*g+1][1], aPh[2], aPl[2]);
            pack_hl(sc[2*g+1][2], sc[2*g+1][3], aPh[3], aPl[3]);
#pragma unroll
            for (int pd = 0; pd < 4; pd++) {
                int rV = pd * 16 + (lane & 15);
                uint32_t voff = rV * 512 +
                    (((s0 + g * 16) * 2 + cadd) ^ ((rV & 7) << 4));
                uint32_t bh[4], bl[4];
                ldsm_x4(bh, sb + AVH + voff);
                ldsm_x4(bl, sb + AVL + voff);
                mma16816(O[2*pd],   aPh, bh[0], bh[2]);
                mma16816(O[2*pd+1], aPh, bh[1], bh[3]);
                mma16816(O[2*pd],   aPh, bl[0], bl[2]);
                mma16816(O[2*pd+1], aPh, bl[1], bl[3]);
                mma16816(O[2*pd],   aPl, bh[0], bh[2]);
                mma16816(O[2*pd+1], aPl, bh[1], bh[3]);
            }
        }
    }

    // ---- epilogue: O/l -> ctx bf16 hi/lo ---------------------------------
    const float i0 = 1.f / l0, i1 = 1.f / l1;
    const size_t gr0 = (size_t)(b * LQ_ + bq + qr + (lane >> 2));
    const size_t gr1 = gr0 + 8;
#pragma unroll
    for (int j = 0; j < 8; j++) {
        int gc = h * HD_ + j * 8 + (lane & 3) * 2;
        uint32_t hh, ll;
        pack_hl(O[j][0] * i0, O[j][1] * i0, hh, ll);
        *(uint32_t*)&ch[gr0 * D_ + gc] = hh;
        *(uint32_t*)&cl[gr0 * D_ + gc] = ll;
        pack_hl(O[j][2] * i1, O[j][3] * i1, hh, ll);
        *(uint32_t*)&ch[gr1 * D_ + gc] = hh;
        *(uint32_t*)&cl[gr1 * D_ + gc] = ll;
    }
}

// ---------------------------------------------------------------------------
// Epilogue: two layer-norms + sigmoid box (unchanged)
// ---------------------------------------------------------------------------
#define OUT_TGT 8388608u
#define OUT_BOX 16777216u

__global__ __launch_bounds__(256)
void ln_box_kernel(const float* __restrict__ ffn, const float* __restrict__ attn,
                   const float* __restrict__ g1, const float* __restrict__ be1,
                   const float* __restrict__ g2, const float* __restrict__ be2,
                   float* __restrict__ out)
{
    __shared__ float red[8];
    __shared__ float bcast;
    const int row = blockIdx.x;
    const int tid = threadIdx.x;
    const int lane = tid & 31, w = tid >> 5;

    float4 x = ((const float4*)(ffn + (size_t)row * D_))[tid];

    float s = x.x + x.y + x.z + x.w;
#pragma unroll
    for (int o = 16; o; o >>= 1) s += __shfl_xor_sync(0xffffffffu, s, o);
    if (lane == 0) red[w] = s;
    __syncthreads();
    if (w == 0) {
        float t = (lane < 8) ? red[lane] : 0.f;
#pragma unroll
        for (int o = 4; o; o >>= 1) t += __shfl_xor_sync(0xffffffffu, t, o);
        if (lane == 0) bcast = t * (1.f / 1024.f);
    }
    __syncthreads();
    const float mean = bcast;
    __syncthreads();

    float dx = x.x - mean, dy = x.y - mean, dz = x.z - mean, dw = x.w - mean;
    float sq = dx * dx + dy * dy + dz * dz + dw * dw;
#pragma unroll
    for (int o = 16; o; o >>= 1) sq += __shfl_xor_sync(0xffffffffu, sq, o);
    if (lane == 0) red[w] = sq;
    __syncthreads();
    if (w == 0) {
        float t = (lane < 8) ? red[lane] : 0.f;
#pragma unroll
        for (int o = 4; o; o >>= 1) t += __shfl_xor_sync(0xffffffffu, t, o);
        if (lane == 0) bcast = rsqrtf(t * (1.f / 1024.f) + 1e-5f);
    }
    __syncthreads();
    const float inv = bcast;

    float4 G1 = ((const float4*)g1)[tid];
    float4 B1 = ((const float4*)be1)[tid];
    float4 G2 = ((const float4*)g2)[tid];
    float4 B2 = ((const float4*)be2)[tid];

    float4 o1, o2;
    o1.x = dx * inv * G1.x + B1.x;  o2.x = dx * inv * G2.x + B2.x;
    o1.y = dy * inv * G1.y + B1.y;  o2.y = dy * inv * G2.y + B2.y;
    o1.z = dz * inv * G1.z + B1.z;  o2.z = dz * inv * G2.z + B2.z;
    o1.w = dw * inv * G1.w + B1.w;  o2.w = dw * inv * G2.w + B2.w;

    ((float4*)out)[(size_t)row * 256 + tid]             = o1;
    ((float4*)(out + OUT_TGT))[(size_t)row * 256 + tid] = o2;

    if (tid == 0) {
        const float* a = attn + (size_t)row * D_;
        float xc = 1.f / (1.f + __expf(-a[0]));
        float yc = 1.f / (1.f + __expf(-a[1]));
        float ww = 1.f / (1.f + __expf(-a[2]));
        float hh = 1.f / (1.f + __expf(-a[3]));
        float4 box = make_float4(xc - ww * 0.5f, yc - hh * 0.5f,
                                 xc + ww * 0.5f, yc + hh * 0.5f);
        *(float4*)(out + OUT_BOX + (size_t)row * 4) = box;
    }
}

// ---------------------------------------------------------------------------
// Launch
// ---------------------------------------------------------------------------
extern "C" void kernel_launch(void* const* d_in, const int* in_sizes, int n_in,
                              void* d_out, int out_size)
{
    const float* memory = (const float*)d_in[0];
    const float* gaze   = (const float*)d_in[1];
    const float* text   = (const float*)d_in[2];
    const float* w_in   = (const float*)d_in[3];
    const float* b_in   = (const float*)d_in[4];
    const float* w_o    = (const float*)d_in[5];
    const float* b_o    = (const float*)d_in[6];
    const float* w1     = (const float*)d_in[7];
    const float* b1     = (const float*)d_in[8];
    const float* w2     = (const float*)d_in[9];
    const float* b2     = (const float*)d_in[10];
    const float* g1     = (const float*)d_in[11];
    const float* be1    = (const float*)d_in[12];
    const float* g2     = (const float*)d_in[13];
    const float* be2    = (const float*)d_in[14];
    float* out = (float*)d_out;

    __nv_bfloat16 *cAh,*cAl,*th,*tl,*wih,*wil,*woh,*wol,*w1h,*w1l,*w2h,*w2l;
    __nv_bfloat16 *qh,*ql,*kvh,*kvl,*chb,*clb,*ah,*al,*mh,*ml;
    float *ATT,*FFN;
    cudaGetSymbolAddress((void**)&cAh, g_cAh); cudaGetSymbolAddress((void**)&cAl, g_cAl);
    cudaGetSymbolAddress((void**)&th,  g_th);  cudaGetSymbolAddress((void**)&tl,  g_tl);
    cudaGetSymbolAddress((void**)&wih, g_wih); cudaGetSymbolAddress((void**)&wil, g_wil);
    cudaGetSymbolAddress((void**)&woh, g_woh); cudaGetSymbolAddress((void**)&wol, g_wol);
    cudaGetSymbolAddress((void**)&w1h, g_w1h); cudaGetSymbolAddress((void**)&w1l, g_w1l);
    cudaGetSymbolAddress((void**)&w2h, g_w2h); cudaGetSymbolAddress((void**)&w2l, g_w2l);
    cudaGetSymbolAddress((void**)&qh,  g_qh);  cudaGetSymbolAddress((void**)&ql,  g_ql);
    cudaGetSymbolAddress((void**)&kvh, g_kvh); cudaGetSymbolAddress((void**)&kvl, g_kvl);
    cudaGetSymbolAddress((void**)&chb, g_ch);  cudaGetSymbolAddress((void**)&clb, g_cl);
    cudaGetSymbolAddress((void**)&ah,  g_ah);  cudaGetSymbolAddress((void**)&al,  g_al);
    cudaGetSymbolAddress((void**)&mh,  g_mh);  cudaGetSymbolAddress((void**)&ml,  g_ml);
    cudaGetSymbolAddress((void**)&ATT, g_att); cudaGetSymbolAddress((void**)&FFN, g_ffn);

    cudaFuncSetAttribute(gemm_bf3,
                         cudaFuncAttributeMaxDynamicSharedMemorySize, G_DSMEM);
    cudaFuncSetAttribute(attn_tc,
                         cudaFuncAttributeMaxDynamicSharedMemorySize, ATT_DSMEM);

    dim3 blk(256), blk512(512);

    // ---- one-time input/weight splits (4 launches) ----
    cvt_concat<<<(MQ_ * 256 + 255) / 256, blk>>>(memory, gaze, cAh, cAl);
    cvt_split <<<(MKV_ * 256 + 255) / 256, blk>>>(text, 1024, th, tl, 1024, MKV_, 256);
    cvt_split <<<(3 * D_ * 256 + 255) / 256, blk>>>(w_in, 1024, wih, wil, 1024, 3 * D_, 256);
    {
        dim3 g3((D_ * 256 + 255) / 256, 3);
        cvt_split3<<<g3, blk>>>(w_o, w1, w2, woh, wol, w1h, w1l, w2h, w2l);
    }

    dim3 gQ(D_ / 128, MQ_ / 256);      // (8, 32)
    dim3 gKV(LDKV_ / 128, MKV_ / 256); // (16, 8) merged K|V

    // Q projection (scale 1/8 folded in), bf16 out only
    gemm_bf3<<<gQ, blk512, G_DSMEM>>>(MQ_, D_, D_, cAh, cAl, wih, wil,
                                      b_in, 0.125f, 0, nullptr, qh, ql, D_);
    // merged K|V projection
    gemm_bf3<<<gKV, blk512, G_DSMEM>>>(MKV_, LDKV_, D_, th, tl,
                                       wih + (size_t)D_ * D_, wil + (size_t)D_ * D_,
                                       b_in + D_, 1.f, 0, nullptr, kvh, kvl, LDKV_);
    // attention -> ctx bf16 hi/lo
    dim3 gA(LQ_ / 128, H_, B_);        // (8, 16, 8)
    attn_tc<<<gA, blk, ATT_DSMEM>>>(qh, ql, kvh, kvl, chb, clb);
    // output projection -> ATT fp32 + bf16
    gemm_bf3<<<gQ, blk512, G_DSMEM>>>(MQ_, D_, D_, chb, clb, woh, wol,
                                      b_o, 1.f, 0, ATT, ah, al, D_);
    // FFN1 (relu) -> bf16 only
    gemm_bf3<<<gQ, blk512, G_DSMEM>>>(MQ_, D_, D_, ah, al, w1h, w1l,
                                      b1, 1.f, 1, nullptr, mh, ml, D_);
    // FFN2 -> fp32 only
    gemm_bf3<<<gQ, blk512, G_DSMEM>>>(MQ_, D_, D_, mh, ml, w2h, w2l,
                                      b2, 1.f, 0, FFN, nullptr, nullptr, D_);

    // layer norms + box proposal
    ln_box_kernel<<<MQ_, blk>>>(FFN, ATT, g1, be1, g2, be2, out);
}

// round 16
// speedup vs baseline: 1.2182x; 1.0848x over previous
#include <cuda_runtime.h>
#include <cuda_bf16.h>
#include <math.h>
#include <stdint.h>

// Problem constants
#define B_   8
#define LQ_  1024
#define S_   256
#define D_   1024
#define H_   16
#define HD_  64
#define MQ_  (B_*LQ_)   // 8192
#define MKV_ (B_*S_)    // 2048
#define LDKV_ 2048      // merged K|V row stride

// ---------------------------------------------------------------------------
// Scratch (static device globals — no allocation in kernel_launch)
// ---------------------------------------------------------------------------
__device__ __nv_bfloat16 g_cAh[MQ_*D_],  g_cAl[MQ_*D_];    // concat(memory,gaze)
__device__ __nv_bfloat16 g_th [MKV_*D_], g_tl [MKV_*D_];   // text
__device__ __nv_bfloat16 g_wih[3*D_*D_], g_wil[3*D_*D_];   // w_in
__device__ __nv_bfloat16 g_woh[D_*D_],   g_wol[D_*D_];
__device__ __nv_bfloat16 g_w1h[D_*D_],   g_w1l[D_*D_];
__device__ __nv_bfloat16 g_w2h[D_*D_],   g_w2l[D_*D_];
__device__ __nv_bfloat16 g_qh [MQ_*D_],  g_ql [MQ_*D_];    // q (pre-scaled 1/8)
__device__ __nv_bfloat16 g_kvh[MKV_*LDKV_], g_kvl[MKV_*LDKV_]; // K|V merged
__device__ __nv_bfloat16 g_ch [MQ_*D_],  g_cl [MQ_*D_];    // ctx
__device__ __nv_bfloat16 g_ah [MQ_*D_],  g_al [MQ_*D_];    // attn_output
__device__ __nv_bfloat16 g_mh [MQ_*D_],  g_ml [MQ_*D_];    // relu mid
__device__ float g_att[MQ_*D_];                            // attn_output fp32
__device__ float g_ffn[MQ_*D_];                            // ffn fp32

// ---------------------------------------------------------------------------
// Baseline-ISA helpers (legal on plain compute_103)
// ---------------------------------------------------------------------------
__device__ __forceinline__ uint32_t smem_u32(const void* p) {
    uint32_t a;
    asm("{ .reg .u64 t; cvta.to.shared.u64 t, %1; cvt.u32.u64 %0, t; }"
        : "=r"(a) : "l"(p));
    return a;
}
__device__ __forceinline__ void ldsm_x4(uint32_t* r, uint32_t addr) {
    asm volatile("ldmatrix.sync.aligned.m8n8.x4.shared.b16 {%0,%1,%2,%3}, [%4];"
                 : "=r"(r[0]), "=r"(r[1]), "=r"(r[2]), "=r"(r[3]) : "r"(addr));
}
__device__ __forceinline__ void ldsm_x4_t(uint32_t* r, uint32_t addr) {
    asm volatile("ldmatrix.sync.aligned.m8n8.x4.trans.shared.b16 {%0,%1,%2,%3}, [%4];"
                 : "=r"(r[0]), "=r"(r[1]), "=r"(r[2]), "=r"(r[3]) : "r"(addr));
}
__device__ __forceinline__ void mma16816(float* d, const uint32_t* a,
                                         uint32_t b0, uint32_t b1) {
    asm volatile(
        "mma.sync.aligned.m16n8k16.row.col.f32.bf16.bf16.f32 "
        "{%0,%1,%2,%3}, {%4,%5,%6,%7}, {%8,%9}, {%0,%1,%2,%3};"
        : "+f"(d[0]), "+f"(d[1]), "+f"(d[2]), "+f"(d[3])
        : "r"(a[0]), "r"(a[1]), "r"(a[2]), "r"(a[3]), "r"(b0), "r"(b1));
}
__device__ __forceinline__ void cp16(uint32_t dst, const void* src) {
    asm volatile("cp.async.cg.shared.global [%0], [%1], 16;"
                 :: "r"(dst), "l"(src));
}
#define CP_COMMIT() asm volatile("cp.async.commit_group;" ::: "memory")
#define CP_WAIT0()  asm volatile("cp.async.wait_group 0;" ::: "memory")

// pack two fp32 into bf16x2 hi + residual-lo bf16x2 (lower half = first arg)
__device__ __forceinline__ void pack_hl(float x, float y,
                                        uint32_t& hi, uint32_t& lo) {
    asm("cvt.rn.bf16x2.f32 %0, %1, %2;" : "=r"(hi) : "f"(y), "f"(x));
    float rx = x - __uint_as_float(hi << 16);
    float ry = y - __uint_as_float(hi & 0xffff0000u);
    asm("cvt.rn.bf16x2.f32 %0, %1, %2;" : "=r"(lo) : "f"(ry), "f"(rx));
}

// ---------------------------------------------------------------------------
// One-time fp32 -> bf16 hi/lo splits
// ---------------------------------------------------------------------------
__global__ void cvt_split(const float* __restrict__ src, int sld,
                          __nv_bfloat16* __restrict__ hi,
                          __nv_bfloat16* __restrict__ lo,
                          int dld, int rows, int cols4)
{
    int idx = blockIdx.x * blockDim.x + threadIdx.x;
    if (idx >= rows * cols4) return;
    int row = idx / cols4, c = idx - row * cols4;
    float4 v = *(const float4*)(src + (size_t)row * sld + c * 4);
    uint32_t h01, h23, l01, l23;
    pack_hl(v.x, v.y, h01, l01);
    pack_hl(v.z, v.w, h23, l23);
    *(uint2*)(hi + (size_t)row * dld + c * 4) = make_uint2(h01, h23);
    *(uint2*)(lo + (size_t)row * dld + c * 4) = make_uint2(l01, l23);
}

// fused concat(memory, gaze) -> hi/lo  (rows MQ_, 256 cols4 of output)
__global__ void cvt_concat(const float* __restrict__ a, const float* __restrict__ b,
                           __nv_bfloat16* __restrict__ hi,
                           __nv_bfloat16* __restrict__ lo)
{
    int idx = blockIdx.x * blockDim.x + threadIdx.x;
    if (idx >= MQ_ * 256) return;
    int row = idx >> 8, c = idx & 255;
    const float* sp = (c < 128) ? a + (size_t)row * 512 + c * 4
                                : b + (size_t)row * 512 + (c - 128) * 4;
    float4 v = *(const float4*)sp;
    uint32_t h01, h23, l01, l23;
    pack_hl(v.x, v.y, h01, l01);
    pack_hl(v.z, v.w, h23, l23);
    *(uint2*)(hi + (size_t)row * D_ + c * 4) = make_uint2(h01, h23);
    *(uint2*)(lo + (size_t)row * D_ + c * 4) = make_uint2(l01, l23);
}

// three same-shape (D_ x D_) weights in one launch, selected by blockIdx.y
__global__ void cvt_split3(const float* __restrict__ s0, const float* __restrict__ s1,
                           const float* __restrict__ s2,
                           __nv_bfloat16* __restrict__ h0, __nv_bfloat16* __restrict__ l0,
                           __nv_bfloat16* __restrict__ h1, __nv_bfloat16* __restrict__ l1,
                           __nv_bfloat16* __restrict__ h2, __nv_bfloat16* __restrict__ l2)
{
    int idx = blockIdx.x * blockDim.x + threadIdx.x;
    if (idx >= D_ * 256) return;
    int which = blockIdx.y;
    const float* src = (which == 0) ? s0 : (which == 1) ? s1 : s2;
    __nv_bfloat16* hi = (which == 0) ? h0 : (which == 1) ? h1 : h2;
    __nv_bfloat16* lo = (which == 0) ? l0 : (which == 1) ? l1 : l2;
    int row = idx >> 8, c = idx & 255;
    float4 v = *(const float4*)(src + (size_t)row * D_ + c * 4);
    uint32_t h01, h23, l01, l23;
    pack_hl(v.x, v.y, h01, l01);
    pack_hl(v.z, v.w, h23, l23);
    *(uint2*)(hi + (size_t)row * D_ + c * 4) = make_uint2(h01, h23);
    *(uint2*)(lo + (size_t)row * D_ + c * 4) = make_uint2(l01, l23);
}

// ---------------------------------------------------------------------------
// gemm_bf3 (256x128 tile): C = act((Ah+Al)(Bh+Bl)^T + bias)*scale
// 512 threads, 16 warps (warp = 32x64), K-chunk 64, XOR-swizzled 128B rows,
// 2-stage cp.async double buffer (2 x 96KB). Single barrier per chunk.
// ---------------------------------------------------------------------------
#define GA_TILE 32768                   // A hi (256 x 64 bf16)
#define GB_TILE 16384                   // B hi (128 x 64 bf16)
#define G_STAGE (2 * GA_TILE + 2 * GB_TILE)   // 98304
#define G_DSMEM (2 * G_STAGE)                 // 196608

__global__ __launch_bounds__(512, 1)
void gemm_bf3(int M, int N, int K,
              const __nv_bfloat16* __restrict__ Ah,
              const __nv_bfloat16* __restrict__ Al,
              const __nv_bfloat16* __restrict__ Bh,
              const __nv_bfloat16* __restrict__ Bl,
              const float* __restrict__ bias, float scale, int act,
              float* __restrict__ Cf,
              __nv_bfloat16* __restrict__ Ch, __nv_bfloat16* __restrict__ Cl,
              int ldc)
{
    extern __shared__ __align__(16) char smc[];
    const uint32_t sb = smem_u32(smc);
    const int tid = threadIdx.x, lane = tid & 31, w = tid >> 5;
    const int m0 = blockIdx.y * 256, n0 = blockIdx.x * 128;
    const int mrow = (w & 7) * 32, ncol = (w >> 3) * 64;

    float acc[2][8][4];
#pragma unroll
    for (int i = 0; i < 2; i++)
#pragma unroll
        for (int j = 0; j < 8; j++)
#pragma unroll
            for (int q = 0; q < 4; q++) acc[i][j][q] = 0.f;

    auto issue = [&](int c, int stage) {
        const int k0 = c * 64;
        const uint32_t st = sb + stage * G_STAGE;
#pragma unroll
        for (int it = 0; it < 4; it++) {
            int e = tid + it * 512;
            int r = e >> 3, cc = e & 7;
            uint32_t off = r * 128 + ((cc * 16) ^ ((r & 7) << 4));
            const size_t ga = (size_t)(m0 + r) * K + k0 + cc * 8;
            cp16(st + off,           Ah + ga);
            cp16(st + GA_TILE + off, Al + ga);
        }
#pragma unroll
        for (int it = 0; it < 2; it++) {
            int e = tid + it * 512;
            int r = e >> 3, cc = e & 7;
            uint32_t off = r * 128 + ((cc * 16) ^ ((r & 7) << 4));
            const size_t gb = (size_t)(n0 + r) * K + k0 + cc * 8;
            cp16(st + 2 * GA_TILE + off,           Bh + gb);
            cp16(st + 2 * GA_TILE + GB_TILE + off, Bl + gb);
        }
    };

    const int NC = K / 64;
    issue(0, 0); CP_COMMIT();

    const int cadd = ((lane >> 4) & 1) * 16;
    for (int c = 0; c < NC; ++c) {
        CP_WAIT0();
        __syncthreads();    // loads of chunk c done AND stage reads of c-1 done
        if (c + 1 < NC) { issue(c + 1, (c + 1) & 1); CP_COMMIT(); }
        const uint32_t st = sb + (c & 1) * G_STAGE;
#pragma unroll
        for (int ks = 0; ks < 4; ks++) {
            uint32_t aH[2][4], aL[2][4];
#pragma unroll
            for (int mi = 0; mi < 2; mi++) {
                int rA = mrow + mi * 16 + (lane & 15);
                uint32_t off = rA * 128 + ((ks * 32 + cadd) ^ ((rA & 7) << 4));
                ldsm_x4(aH[mi], st + off);
                ldsm_x4(aL[mi], st + GA_TILE + off);
            }
#pragma unroll
            for (int j = 0; j < 4; j++) {
                int rB = ncol + j * 16 + (lane & 15);
                uint32_t off = rB * 128 + ((ks * 32 + cadd) ^ ((rB & 7) << 4));
                uint32_t bh[4], bl[4];
                ldsm_x4(bh, st + 2 * GA_TILE + off);
                ldsm_x4(bl, st + 2 * GA_TILE + GB_TILE + off);
#pragma unroll
                for (int mi = 0; mi < 2; mi++) {
                    mma16816(acc[mi][2*j],   aH[mi], bh[0], bh[2]);
                    mma16816(acc[mi][2*j+1], aH[mi], bh[1], bh[3]);
                    mma16816(acc[mi][2*j],   aH[mi], bl[0], bl[2]);
                    mma16816(acc[mi][2*j+1], aH[mi], bl[1], bl[3]);
                    mma16816(acc[mi][2*j],   aL[mi], bh[0], bh[2]);
                    mma16816(acc[mi][2*j+1], aL[mi], bh[1], bh[3]);
                }
            }
        }
        // no trailing sync: next iteration's top barrier orders stage reuse
    }

    // epilogue: bias/relu/scale -> fp32 and/or bf16 hi/lo
    const int r0 = lane >> 2, c0 = (lane & 3) * 2;
#pragma unroll
    for (int mi = 0; mi < 2; mi++) {
#pragma unroll
        for (int ni = 0; ni < 8; ni++) {
            int gr = m0 + mrow + mi * 16 + r0;
            int gc = n0 + ncol + ni * 8 + c0;
            float b0v = bias[gc], b1v = bias[gc + 1];
            float v0 = acc[mi][ni][0] + b0v, v1 = acc[mi][ni][1] + b1v;
            float v2 = acc[mi][ni][2] + b0v, v3 = acc[mi][ni][3] + b1v;
            if (act) {
                v0 = fmaxf(v0, 0.f); v1 = fmaxf(v1, 0.f);
                v2 = fmaxf(v2, 0.f); v3 = fmaxf(v3, 0.f);
            }
            v0 *= scale; v1 *= scale; v2 *= scale; v3 *= scale;
            if (Cf) {
                *(float2*)&Cf[(size_t)gr * ldc + gc]       = make_float2(v0, v1);
                *(float2*)&Cf[(size_t)(gr + 8) * ldc + gc] = make_float2(v2, v3);
            }
            if (Ch) {
                uint32_t hh, ll;
                pack_hl(v0, v1, hh, ll);
                *(uint32_t*)&Ch[(size_t)gr * ldc + gc] = hh;
                *(uint32_t*)&Cl[(size_t)gr * ldc + gc] = ll;
                pack_hl(v2, v3, hh, ll);
                *(uint32_t*)&Ch[(size_t)(gr + 8) * ldc + gc] = hh;
                *(uint32_t*)&Cl[(size_t)(gr + 8) * ldc + gc] = ll;
            }
        }
    }
}

// ---------------------------------------------------------------------------
// HMMA flash attention. V now stored row-major [s][d] in smem (cp.async 16B
// copies, XOR swizzle) and PV B-frags loaded via ldmatrix.trans — removes the
// 8-way-conflicted scalar transpose. Same MMA sequence/products as R13-R15.
// ---------------------------------------------------------------------------
#define AQH 0
#define AQL 16384
#define AKH 32768
#define AKL 65536
#define AVH 98304
#define AVL 131072
#define ATT_DSMEM 163840

__global__ __launch_bounds__(256, 1)
void attn_tc(const __nv_bfloat16* __restrict__ qh, const __nv_bfloat16* __restrict__ ql,
             const __nv_bfloat16* __restrict__ kvh, const __nv_bfloat16* __restrict__ kvl,
             __nv_bfloat16* __restrict__ ch, __nv_bfloat16* __restrict__ cl)
{
    extern __shared__ __align__(16) char smc[];
    const uint32_t sb = smem_u32(smc);
    const int tid = threadIdx.x, lane = tid & 31, w = tid >> 5;
    const int bq = blockIdx.x * 128;
    const int h  = blockIdx.y, b = blockIdx.z;

    // ---- cp.async fills: Q[128x64], K[256x64], V[256x64] (all hi+lo) ------
    const size_t qbase = ((size_t)(b * LQ_ + bq)) * D_ + h * HD_;
    for (int e = tid; e < 1024; e += 256) {
        int r = e >> 3, c = e & 7;
        uint32_t off = r * 128 + ((c * 16) ^ ((r & 7) << 4));
        cp16(sb + AQH + off, qh + qbase + (size_t)r * D_ + c * 8);
        cp16(sb + AQL + off, ql + qbase + (size_t)r * D_ + c * 8);
    }
    const size_t kbase = ((size_t)(b * S_)) * LDKV_ + h * HD_;
    for (int e = tid; e < 2048; e += 256) {
        int r = e >> 3, c = e & 7;
        uint32_t off = r * 128 + ((c * 16) ^ ((r & 7) << 4));
        cp16(sb + AKH + off, kvh + kbase + (size_t)r * LDKV_ + c * 8);
        cp16(sb + AKL + off, kvl + kbase + (size_t)r * LDKV_ + c * 8);
    }
    for (int e = tid; e < 2048; e += 256) {     // V rows s (row-major [s][d])
        int r = e >> 3, c = e & 7;
        uint32_t off = r * 128 + ((c * 16) ^ ((r & 7) << 4));
        cp16(sb + AVH + off, kvh + kbase + (size_t)r * LDKV_ + 1024 + c * 8);
        cp16(sb + AVL + off, kvl + kbase + (size_t)r * LDKV_ + 1024 + c * 8);
    }
    CP_COMMIT();
    CP_WAIT0();
    __syncthreads();

    // ---- per-warp flash loop ---------------------------------------------
    const int qr = w * 16;
    const int rA = qr + (lane & 15);
    const int cadd = ((lane >> 4) & 1) * 16;

    float O[8][4];
#pragma unroll
    for (int j = 0; j < 8; j++)
#pragma unroll
        for (int q = 0; q < 4; q++) O[j][q] = 0.f;
    float m0 = -1e30f, m1 = -1e30f, l0 = 0.f, l1 = 0.f;

    for (int t = 0; t < 4; ++t) {
        const int s0 = t * 64;
        float sc[8][4];
#pragma unroll
        for (int j = 0; j < 8; j++)
#pragma unroll
            for (int q = 0; q < 4; q++) sc[j][q] = 0.f;

        // scores = (Qh+Ql)(Kh+Kl)^T  (Q pre-scaled by 1/8)
#pragma unroll
        for (int ks = 0; ks < 4; ks++) {
            uint32_t qoff = rA * 128 + ((ks * 32 + cadd) ^ ((rA & 7) << 4));
            uint32_t aH[4], aL[4];
            ldsm_x4(aH, sb + AQH + qoff);
            ldsm_x4(aL, sb + AQL + qoff);
#pragma unroll
            for (int p = 0; p < 4; p++) {
                int rB = s0 + p * 16 + (lane & 15);
                uint32_t boff = rB * 128 + ((ks * 32 + cadd) ^ ((rB & 7) << 4));
                uint32_t bh[4], bl[4];
                ldsm_x4(bh, sb + AKH + boff);
                ldsm_x4(bl, sb + AKL + boff);
                mma16816(sc[2*p],   aH, bh[0], bh[2]);
                mma16816(sc[2*p+1], aH, bh[1], bh[3]);
                mma16816(sc[2*p],   aH, bl[0], bl[2]);
                mma16816(sc[2*p+1], aH, bl[1], bl[3]);
                mma16816(sc[2*p],   aL, bh[0], bh[2]);
                mma16816(sc[2*p+1], aL, bh[1], bh[3]);
            }
        }

        // online softmax (rows r0 = lane>>2 and r0+8; quad = lanes xor 1,2)
        float mx0 = -1e30f, mx1 = -1e30f;
#pragma unroll
        for (int j = 0; j < 8; j++) {
            mx0 = fmaxf(mx0, fmaxf(sc[j][0], sc[j][1]));
            mx1 = fmaxf(mx1, fmaxf(sc[j][2], sc[j][3]));
        }
        mx0 = fmaxf(mx0, __shfl_xor_sync(0xffffffffu, mx0, 1));
        mx0 = fmaxf(mx0, __shfl_xor_sync(0xffffffffu, mx0, 2));
        mx1 = fmaxf(mx1, __shfl_xor_sync(0xffffffffu, mx1, 1));
        mx1 = fmaxf(mx1, __shfl_xor_sync(0xffffffffu, mx1, 2));
        float mn0 = fmaxf(m0, mx0), mn1 = fmaxf(m1, mx1);
        float a0 = __expf(m0 - mn0), a1 = __expf(m1 - mn1);
        m0 = mn0; m1 = mn1;
        float ls0 = 0.f, ls1 = 0.f;
#pragma unroll
        for (int j = 0; j < 8; j++) {
            sc[j][0] = __expf(sc[j][0] - m0);
            sc[j][1] = __expf(sc[j][1] - m0);
            sc[j][2] = __expf(sc[j][2] - m1);
            sc[j][3] = __expf(sc[j][3] - m1);
            ls0 += sc[j][0] + sc[j][1];
            ls1 += sc[j][2] + sc[j][3];
        }
        ls0 += __shfl_xor_sync(0xffffffffu, ls0, 1);
        ls0 += __shfl_xor_sync(0xffffffffu, ls0, 2);
        ls1 += __shfl_xor_sync(0xffffffffu, ls1, 1);
        ls1 += __shfl_xor_sync(0xffffffffu, ls1, 2);
        l0 = l0 * a0 + ls0;
        l1 = l1 * a1 + ls1;
#pragma unroll
        for (int j = 0; j < 8; j++) {
            O[j][0] *= a0; O[j][1] *= a0;
            O[j][2] *= a1; O[j][3] *= a1;
        }

        // PV: O += (Ph+Pl)(V)  — B-frags via ldmatrix.trans on [s][d] rows.
        // lanes 0-15 -> s-rows (k), byte offset pd*32 (+16 for lanes 16-31):
        // post-trans regs r0=(d0-7,s0-7) r1=(d0-7,s8-15) r2=(d8-15,s0-7)
        // r3=(d8-15,s8-15) -> (b0,b1) = (r0,r1) / (r2,r3).
#pragma unroll
        for (int g = 0; g < 4; g++) {
            uint32_t aPh[4], aPl[4];
            pack_hl(sc[2*g][0],   sc[2*g][1],   aPh[0], aPl[0]);
            pack_hl(sc[2*g][2],   sc[2*g][3],   aPh[1], aPl[1]);
            pack_hl(sc[2*g+1][0], sc[2*g+1][1], aPh[2], aPl[2]);
            pack_hl(sc[2*g+1][2], sc[2*g+1][3], aPh[3], aPl[3]);
            const int rV = s0 + g * 16 + (lane & 15);
#pragma unroll
            for (int pd = 0; pd < 4; pd++) {
                uint32_t voff = rV * 128 + ((pd * 32 + cadd) ^ ((rV & 7) << 4));
                uint32_t bh[4], bl[4];
                ldsm_x4_t(bh, sb + AVH + voff);
                ldsm_x4_t(bl, sb + AVL + voff);
                mma16816(O[2*pd],   aPh, bh[0], bh[1]);
                mma16816(O[2*pd+1], aPh, bh[2], bh[3]);
                mma16816(O[2*pd],   aPh, bl[0], bl[1]);
                mma16816(O[2*pd+1], aPh, bl[2], bl[3]);
                mma16816(O[2*pd],   aPl, bh[0], bh[1]);
                mma16816(O[2*pd+1], aPl, bh[2], bh[3]);
            }
        }
    }

    // ---- epilogue: O/l -> ctx bf16 hi/lo ---------------------------------
    const float i0 = 1.f / l0, i1 = 1.f / l1;
    const size_t gr0 = (size_t)(b * LQ_ + bq + qr + (lane >> 2));
    const size_t gr1 = gr0 + 8;
#pragma unroll
    for (int j = 0; j < 8; j++) {
        int gc = h * HD_ + j * 8 + (lane & 3) * 2;
        uint32_t hh, ll;
        pack_hl(O[j][0] * i0, O[j][1] * i0, hh, ll);
        *(uint32_t*)&ch[gr0 * D_ + gc] = hh;
        *(uint32_t*)&cl[gr0 * D_ + gc] = ll;
        pack_hl(O[j][2] * i1, O[j][3] * i1, hh, ll);
        *(uint32_t*)&ch[gr1 * D_ + gc] = hh;
        *(uint32_t*)&cl[gr1 * D_ + gc] = ll;
    }
}

// ---------------------------------------------------------------------------
// Epilogue: two layer-norms + sigmoid box (unchanged)
// ---------------------------------------------------------------------------
#define OUT_TGT 8388608u
#define OUT_BOX 16777216u

__global__ __launch_bounds__(256)
void ln_box_kernel(const float* __restrict__ ffn, const float* __restrict__ attn,
                   const float* __restrict__ g1, const float* __restrict__ be1,
                   const float* __restrict__ g2, const float* __restrict__ be2,
                   float* __restrict__ out)
{
    __shared__ float red[8];
    __shared__ float bcast;
    const int row = blockIdx.x;
    const int tid = threadIdx.x;
    const int lane = tid & 31, w = tid >> 5;

    float4 x = ((const float4*)(ffn + (size_t)row * D_))[tid];

    float s = x.x + x.y + x.z + x.w;
#pragma unroll
    for (int o = 16; o; o >>= 1) s += __shfl_xor_sync(0xffffffffu, s, o);
    if (lane == 0) red[w] = s;
    __syncthreads();
    if (w == 0) {
        float t = (lane < 8) ? red[lane] : 0.f;
#pragma unroll
        for (int o = 4; o; o >>= 1) t += __shfl_xor_sync(0xffffffffu, t, o);
        if (lane == 0) bcast = t * (1.f / 1024.f);
    }
    __syncthreads();
    const float mean = bcast;
    __syncthreads();

    float dx = x.x - mean, dy = x.y - mean, dz = x.z - mean, dw = x.w - mean;
    float sq = dx * dx + dy * dy + dz * dz + dw * dw;
#pragma unroll
    for (int o = 16; o; o >>= 1) sq += __shfl_xor_sync(0xffffffffu, sq, o);
    if (lane == 0) red[w] = sq;
    __syncthreads();
    if (w == 0) {
        float t = (lane < 8) ? red[lane] : 0.f;
#pragma unroll
        for (int o = 4; o; o >>= 1) t += __shfl_xor_sync(0xffffffffu, t, o);
        if (lane == 0) bcast = rsqrtf(t * (1.f / 1024.f) + 1e-5f);
    }
    __syncthreads();
    const float inv = bcast;

    float4 G1 = ((const float4*)g1)[tid];
    float4 B1 = ((const float4*)be1)[tid];
    float4 G2 = ((const float4*)g2)[tid];
    float4 B2 = ((const float4*)be2)[tid];

    float4 o1, o2;
    o1.x = dx * inv * G1.x + B1.x;  o2.x = dx * inv * G2.x + B2.x;
    o1.y = dy * inv * G1.y + B1.y;  o2.y = dy * inv * G2.y + B2.y;
    o1.z = dz * inv * G1.z + B1.z;  o2.z = dz * inv * G2.z + B2.z;
    o1.w = dw * inv * G1.w + B1.w;  o2.w = dw * inv * G2.w + B2.w;

    ((float4*)out)[(size_t)row * 256 + tid]             = o1;
    ((float4*)(out + OUT_TGT))[(size_t)row * 256 + tid] = o2;

    if (tid == 0) {
        const float* a = attn + (size_t)row * D_;
        float xc = 1.f / (1.f + __expf(-a[0]));
        float yc = 1.f / (1.f + __expf(-a[1]));
        float ww = 1.f / (1.f + __expf(-a[2]));
        float hh = 1.f / (1.f + __expf(-a[3]));
        float4 box = make_float4(xc - ww * 0.5f, yc - hh * 0.5f,
                                 xc + ww * 0.5f, yc + hh * 0.5f);
        *(float4*)(out + OUT_BOX + (size_t)row * 4) = box;
    }
}

// ---------------------------------------------------------------------------
// Launch
// ---------------------------------------------------------------------------
extern "C" void kernel_launch(void* const* d_in, const int* in_sizes, int n_in,
                              void* d_out, int out_size)
{
    const float* memory = (const float*)d_in[0];
    const float* gaze   = (const float*)d_in[1];
    const float* text   = (const float*)d_in[2];
    const float* w_in   = (const float*)d_in[3];
    const float* b_in   = (const float*)d_in[4];
    const float* w_o    = (const float*)d_in[5];
    const float* b_o    = (const float*)d_in[6];
    const float* w1     = (const float*)d_in[7];
    const float* b1     = (const float*)d_in[8];
    const float* w2     = (const float*)d_in[9];
    const float* b2     = (const float*)d_in[10];
    const float* g1     = (const float*)d_in[11];
    const float* be1    = (const float*)d_in[12];
    const float* g2     = (const float*)d_in[13];
    const float* be2    = (const float*)d_in[14];
    float* out = (float*)d_out;

    __nv_bfloat16 *cAh,*cAl,*th,*tl,*wih,*wil,*woh,*wol,*w1h,*w1l,*w2h,*w2l;
    __nv_bfloat16 *qh,*ql,*kvh,*kvl,*chb,*clb,*ah,*al,*mh,*ml;
    float *ATT,*FFN;
    cudaGetSymbolAddress((void**)&cAh, g_cAh); cudaGetSymbolAddress((void**)&cAl, g_cAl);
    cudaGetSymbolAddress((void**)&th,  g_th);  cudaGetSymbolAddress((void**)&tl,  g_tl);
    cudaGetSymbolAddress((void**)&wih, g_wih); cudaGetSymbolAddress((void**)&wil, g_wil);
    cudaGetSymbolAddress((void**)&woh, g_woh); cudaGetSymbolAddress((void**)&wol, g_wol);
    cudaGetSymbolAddress((void**)&w1h, g_w1h); cudaGetSymbolAddress((void**)&w1l, g_w1l);
    cudaGetSymbolAddress((void**)&w2h, g_w2h); cudaGetSymbolAddress((void**)&w2l, g_w2l);
    cudaGetSymbolAddress((void**)&qh,  g_qh);  cudaGetSymbolAddress((void**)&ql,  g_ql);
    cudaGetSymbolAddress((void**)&kvh, g_kvh); cudaGetSymbolAddress((void**)&kvl, g_kvl);
    cudaGetSymbolAddress((void**)&chb, g_ch);  cudaGetSymbolAddress((void**)&clb, g_cl);
    cudaGetSymbolAddress((void**)&ah,  g_ah);  cudaGetSymbolAddress((void**)&al,  g_al);
    cudaGetSymbolAddress((void**)&mh,  g_mh);  cudaGetSymbolAddress((void**)&ml,  g_ml);
    cudaGetSymbolAddress((void**)&ATT, g_att); cudaGetSymbolAddress((void**)&FFN, g_ffn);

    cudaFuncSetAttribute(gemm_bf3,
                         cudaFuncAttributeMaxDynamicSharedMemorySize, G_DSMEM);
    cudaFuncSetAttribute(attn_tc,
                         cudaFuncAttributeMaxDynamicSharedMemorySize, ATT_DSMEM);

    dim3 blk(256), blk512(512);

    // ---- one-time input/weight splits (4 launches) ----
    cvt_concat<<<(MQ_ * 256 + 255) / 256, blk>>>(memory, gaze, cAh, cAl);
    cvt_split <<<(MKV_ * 256 + 255) / 256, blk>>>(text, 1024, th, tl, 1024, MKV_, 256);
    cvt_split <<<(3 * D_ * 256 + 255) / 256, blk>>>(w_in, 1024, wih, wil, 1024, 3 * D_, 256);
    {
        dim3 g3((D_ * 256 + 255) / 256, 3);
        cvt_split3<<<g3, blk>>>(w_o, w1, w2, woh, wol, w1h, w1l, w2h, w2l);
    }

    dim3 gQ(D_ / 128, MQ_ / 256);      // (8, 32)
    dim3 gKV(LDKV_ / 128, MKV_ / 256); // (16, 8) merged K|V

    // Q projection (scale 1/8 folded in), bf16 out only
    gemm_bf3<<<gQ, blk512, G_DSMEM>>>(MQ_, D_, D_, cAh, cAl, wih, wil,
                                      b_in, 0.125f, 0, nullptr, qh, ql, D_);
    // merged K|V projection
    gemm_bf3<<<gKV, blk512, G_DSMEM>>>(MKV_, LDKV_, D_, th, tl,
                                       wih + (size_t)D_ * D_, wil + (size_t)D_ * D_,
                                       b_in + D_, 1.f, 0, nullptr, kvh, kvl, LDKV_);
    // attention -> ctx bf16 hi/lo
    dim3 gA(LQ_ / 128, H_, B_);        // (8, 16, 8)
    attn_tc<<<gA, blk, ATT_DSMEM>>>(qh, ql, kvh, kvl, chb, clb);
    // output projection -> ATT fp32 + bf16
    gemm_bf3<<<gQ, blk512, G_DSMEM>>>(MQ_, D_, D_, chb, clb, woh, wol,
                                      b_o, 1.f, 0, ATT, ah, al, D_);
    // FFN1 (relu) -> bf16 only
    gemm_bf3<<<gQ, blk512, G_DSMEM>>>(MQ_, D_, D_, ah, al, w1h, w1l,
                                      b1, 1.f, 1, nullptr, mh, ml, D_);
    // FFN2 -> fp32 only
    gemm_bf3<<<gQ, blk512, G_DSMEM>>>(MQ_, D_, D_, mh, ml, w2h, w2l,
                                      b2, 1.f, 0, FFN, nullptr, nullptr, D_);

    // layer norms + box proposal
    ln_box_kernel<<<MQ_, blk>>>(FFN, ATT, g1, be1, g2, be2, out);
}

// round 17
// speedup vs baseline: 1.2315x; 1.0108x over previous
#include <cuda_runtime.h>
#include <cuda_bf16.h>
#include <math.h>
#include <stdint.h>

// Problem constants
#define B_   8
#define LQ_  1024
#define S_   256
#define D_   1024
#define H_   16
#define HD_  64
#define MQ_  (B_*LQ_)   // 8192
#define MKV_ (B_*S_)    // 2048
#define LDKV_ 2048      // merged K|V row stride

// ---------------------------------------------------------------------------
// Scratch (static device globals — no allocation in kernel_launch)
// ---------------------------------------------------------------------------
__device__ __nv_bfloat16 g_cAh[MQ_*D_],  g_cAl[MQ_*D_];    // concat(memory,gaze)
__device__ __nv_bfloat16 g_th [MKV_*D_], g_tl [MKV_*D_];   // text
__device__ __nv_bfloat16 g_wih[3*D_*D_], g_wil[3*D_*D_];   // w_in
__device__ __nv_bfloat16 g_woh[D_*D_],   g_wol[D_*D_];
__device__ __nv_bfloat16 g_w1h[D_*D_],   g_w1l[D_*D_];
__device__ __nv_bfloat16 g_w2h[D_*D_],   g_w2l[D_*D_];
__device__ __nv_bfloat16 g_qh [MQ_*D_],  g_ql [MQ_*D_];    // q (pre-scaled 1/8)
__device__ __nv_bfloat16 g_kvh[MKV_*LDKV_], g_kvl[MKV_*LDKV_]; // K|V merged
__device__ __nv_bfloat16 g_ch [MQ_*D_],  g_cl [MQ_*D_];    // ctx
__device__ __nv_bfloat16 g_ah [MQ_*D_],  g_al [MQ_*D_];    // attn_output
__device__ __nv_bfloat16 g_mh [MQ_*D_],  g_ml [MQ_*D_];    // relu mid
__device__ float g_att[MQ_*D_];                            // attn_output fp32
__device__ float g_ffn[MQ_*D_];                            // ffn fp32

// ---------------------------------------------------------------------------
// Baseline-ISA helpers (legal on plain compute_103)
// ---------------------------------------------------------------------------
__device__ __forceinline__ uint32_t smem_u32(const void* p) {
    uint32_t a;
    asm("{ .reg .u64 t; cvta.to.shared.u64 t, %1; cvt.u32.u64 %0, t; }"
        : "=r"(a) : "l"(p));
    return a;
}
__device__ __forceinline__ void ldsm_x4(uint32_t* r, uint32_t addr) {
    asm volatile("ldmatrix.sync.aligned.m8n8.x4.shared.b16 {%0,%1,%2,%3}, [%4];"
                 : "=r"(r[0]), "=r"(r[1]), "=r"(r[2]), "=r"(r[3]) : "r"(addr));
}
__device__ __forceinline__ void ldsm_x4_t(uint32_t* r, uint32_t addr) {
    asm volatile("ldmatrix.sync.aligned.m8n8.x4.trans.shared.b16 {%0,%1,%2,%3}, [%4];"
                 : "=r"(r[0]), "=r"(r[1]), "=r"(r[2]), "=r"(r[3]) : "r"(addr));
}
__device__ __forceinline__ void mma16816(float* d, const uint32_t* a,
                                         uint32_t b0, uint32_t b1) {
    asm volatile(
        "mma.sync.aligned.m16n8k16.row.col.f32.bf16.bf16.f32 "
        "{%0,%1,%2,%3}, {%4,%5,%6,%7}, {%8,%9}, {%0,%1,%2,%3};"
        : "+f"(d[0]), "+f"(d[1]), "+f"(d[2]), "+f"(d[3])
        : "r"(a[0]), "r"(a[1]), "r"(a[2]), "r"(a[3]), "r"(b0), "r"(b1));
}
__device__ __forceinline__ void cp16(uint32_t dst, const void* src) {
    asm volatile("cp.async.cg.shared.global [%0], [%1], 16;"
                 :: "r"(dst), "l"(src));
}
#define CP_COMMIT() asm volatile("cp.async.commit_group;" ::: "memory")
#define CP_WAIT0()  asm volatile("cp.async.wait_group 0;" ::: "memory")

// pack two fp32 into bf16x2 hi + residual-lo bf16x2 (lower half = first arg)
__device__ __forceinline__ void pack_hl(float x, float y,
                                        uint32_t& hi, uint32_t& lo) {
    asm("cvt.rn.bf16x2.f32 %0, %1, %2;" : "=r"(hi) : "f"(y), "f"(x));
    float rx = x - __uint_as_float(hi << 16);
    float ry = y - __uint_as_float(hi & 0xffff0000u);
    asm("cvt.rn.bf16x2.f32 %0, %1, %2;" : "=r"(lo) : "f"(ry), "f"(rx));
}

// split one float4 -> hi/lo bf16x2 pairs at dst
__device__ __forceinline__ void split4(const float* sp,
                                       __nv_bfloat16* hi, __nv_bfloat16* lo) {
    float4 v = *(const float4*)sp;
    uint32_t h01, h23, l01, l23;
    pack_hl(v.x, v.y, h01, l01);
    pack_hl(v.z, v.w, h23, l23);
    *(uint2*)hi = make_uint2(h01, h23);
    *(uint2*)lo = make_uint2(l01, l23);
}

// ---------------------------------------------------------------------------
// One fused fp32 -> bf16 hi/lo split kernel for ALL inputs/weights.
// Region sizes are multiples of 256 so a block never straddles regions.
// ---------------------------------------------------------------------------
#define CVT_N0 (MQ_ * 256)        // concat(memory,gaze)  2,097,152
#define CVT_N1 (MKV_ * 256)       // text                   524,288
#define CVT_N2 (3 * D_ * 256)     // w_in                   786,432
#define CVT_N3 (D_ * 256)         // w_o / w1 / w2          262,144
#define CVT_TOTAL (CVT_N0 + CVT_N1 + CVT_N2 + 3 * CVT_N3)  // 4,194,304

__global__ void cvt_all(const float* __restrict__ memory, const float* __restrict__ gaze,
                        const float* __restrict__ text,   const float* __restrict__ w_in,
                        const float* __restrict__ w_o,    const float* __restrict__ w1,
                        const float* __restrict__ w2,
                        __nv_bfloat16* cAh, __nv_bfloat16* cAl,
                        __nv_bfloat16* th,  __nv_bfloat16* tl,
                        __nv_bfloat16* wih, __nv_bfloat16* wil,
                        __nv_bfloat16* woh, __nv_bfloat16* wol,
                        __nv_bfloat16* w1h, __nv_bfloat16* w1l,
                        __nv_bfloat16* w2h, __nv_bfloat16* w2l)
{
    int idx = blockIdx.x * 256 + threadIdx.x;
    if (idx < CVT_N0) {                       // concat(memory, gaze)
        int row = idx >> 8, c = idx & 255;
        const float* sp = (c < 128) ? memory + (size_t)row * 512 + c * 4
                                    : gaze + (size_t)row * 512 + (c - 128) * 4;
        split4(sp, cAh + (size_t)row * D_ + c * 4, cAl + (size_t)row * D_ + c * 4);
        return;
    }
    idx -= CVT_N0;
    if (idx < CVT_N1) {                       // text
        int row = idx >> 8, c = idx & 255;
        split4(text + (size_t)row * D_ + c * 4,
               th + (size_t)row * D_ + c * 4, tl + (size_t)row * D_ + c * 4);
        return;
    }
    idx -= CVT_N1;
    if (idx < CVT_N2) {                       // w_in
        int row = idx >> 8, c = idx & 255;
        split4(w_in + (size_t)row * D_ + c * 4,
               wih + (size_t)row * D_ + c * 4, wil + (size_t)row * D_ + c * 4);
        return;
    }
    idx -= CVT_N2;
    const float* src; __nv_bfloat16 *hi, *lo;
    if (idx < CVT_N3)      { src = w_o; hi = woh; lo = wol; }
    else if (idx < 2*CVT_N3){ idx -= CVT_N3;   src = w1; hi = w1h; lo = w1l; }
    else                   { idx -= 2*CVT_N3; src = w2; hi = w2h; lo = w2l; }
    int row = idx >> 8, c = idx & 255;
    split4(src + (size_t)row * D_ + c * 4,
           hi + (size_t)row * D_ + c * 4, lo + (size_t)row * D_ + c * 4);
}

// ---------------------------------------------------------------------------
// GEMM core (256x128 tile): C = act((Ah+Al)(Bh+Bl)^T + bias)*scale
// 512 threads, 16 warps (warp = 32x64), K-chunk 64, XOR-swizzled 128B rows,
// 2-stage cp.async double buffer. Single barrier per chunk.
// ---------------------------------------------------------------------------
#define GA_TILE 32768                   // A hi (256 x 64 bf16)
#define GB_TILE 16384                   // B hi (128 x 64 bf16)
#define G_STAGE (2 * GA_TILE + 2 * GB_TILE)   // 98304
#define G_DSMEM (2 * G_STAGE)                 // 196608

__device__ __forceinline__
void gemm_core(uint32_t sb, int m0, int n0, int K,
               const __nv_bfloat16* __restrict__ Ah,
               const __nv_bfloat16* __restrict__ Al,
               const __nv_bfloat16* __restrict__ Bh,
               const __nv_bfloat16* __restrict__ Bl,
               const float* __restrict__ bias, float scale, int act,
               float* __restrict__ Cf,
               __nv_bfloat16* __restrict__ Ch, __nv_bfloat16* __restrict__ Cl,
               int ldc)
{
    const int tid = threadIdx.x, lane = tid & 31, w = tid >> 5;
    const int mrow = (w & 7) * 32, ncol = (w >> 3) * 64;

    float acc[2][8][4];
#pragma unroll
    for (int i = 0; i < 2; i++)
#pragma unroll
        for (int j = 0; j < 8; j++)
#pragma unroll
            for (int q = 0; q < 4; q++) acc[i][j][q] = 0.f;

    auto issue = [&](int c, int stage) {
        const int k0 = c * 64;
        const uint32_t st = sb + stage * G_STAGE;
#pragma unroll
        for (int it = 0; it < 4; it++) {
            int e = tid + it * 512;
            int r = e >> 3, cc = e & 7;
            uint32_t off = r * 128 + ((cc * 16) ^ ((r & 7) << 4));
            const size_t ga = (size_t)(m0 + r) * K + k0 + cc * 8;
            cp16(st + off,           Ah + ga);
            cp16(st + GA_TILE + off, Al + ga);
        }
#pragma unroll
        for (int it = 0; it < 2; it++) {
            int e = tid + it * 512;
            int r = e >> 3, cc = e & 7;
            uint32_t off = r * 128 + ((cc * 16) ^ ((r & 7) << 4));
            const size_t gb = (size_t)(n0 + r) * K + k0 + cc * 8;
            cp16(st + 2 * GA_TILE + off,           Bh + gb);
            cp16(st + 2 * GA_TILE + GB_TILE + off, Bl + gb);
        }
    };

    const int NC = K / 64;
    issue(0, 0); CP_COMMIT();

    const int cadd = ((lane >> 4) & 1) * 16;
    for (int c = 0; c < NC; ++c) {
        CP_WAIT0();
        __syncthreads();    // loads of chunk c done AND stage reads of c-1 done
        if (c + 1 < NC) { issue(c + 1, (c + 1) & 1); CP_COMMIT(); }
        const uint32_t st = sb + (c & 1) * G_STAGE;
#pragma unroll
        for (int ks = 0; ks < 4; ks++) {
            uint32_t aH[2][4], aL[2][4];
#pragma unroll
            for (int mi = 0; mi < 2; mi++) {
                int rA = mrow + mi * 16 + (lane & 15);
                uint32_t off = rA * 128 + ((ks * 32 + cadd) ^ ((rA & 7) << 4));
                ldsm_x4(aH[mi], st + off);
                ldsm_x4(aL[mi], st + GA_TILE + off);
            }
#pragma unroll
            for (int j = 0; j < 4; j++) {
                int rB = ncol + j * 16 + (lane & 15);
                uint32_t off = rB * 128 + ((ks * 32 + cadd) ^ ((rB & 7) << 4));
                uint32_t bh[4], bl[4];
                ldsm_x4(bh, st + 2 * GA_TILE + off);
                ldsm_x4(bl, st + 2 * GA_TILE + GB_TILE + off);
#pragma unroll
                for (int mi = 0; mi < 2; mi++) {
                    mma16816(acc[mi][2*j],   aH[mi], bh[0], bh[2]);
                    mma16816(acc[mi][2*j+1], aH[mi], bh[1], bh[3]);
                    mma16816(acc[mi][2*j],   aH[mi], bl[0], bl[2]);
                    mma16816(acc[mi][2*j+1], aH[mi], bl[1], bl[3]);
                    mma16816(acc[mi][2*j],   aL[mi], bh[0], bh[2]);
                    mma16816(acc[mi][2*j+1], aL[mi], bh[1], bh[3]);
                }
            }
        }
        // no trailing sync: next iteration's top barrier orders stage reuse
    }

    // epilogue: bias/relu/scale -> fp32 and/or bf16 hi/lo
    const int r0 = lane >> 2, c0 = (lane & 3) * 2;
#pragma unroll
    for (int mi = 0; mi < 2; mi++) {
#pragma unroll
        for (int ni = 0; ni < 8; ni++) {
            int gr = m0 + mrow + mi * 16 + r0;
            int gc = n0 + ncol + ni * 8 + c0;
            float b0v = bias[gc], b1v = bias[gc + 1];
            float v0 = acc[mi][ni][0] + b0v, v1 = acc[mi][ni][1] + b1v;
            float v2 = acc[mi][ni][2] + b0v, v3 = acc[mi][ni][3] + b1v;
            if (act) {
                v0 = fmaxf(v0, 0.f); v1 = fmaxf(v1, 0.f);
                v2 = fmaxf(v2, 0.f); v3 = fmaxf(v3, 0.f);
            }
            v0 *= scale; v1 *= scale; v2 *= scale; v3 *= scale;
            if (Cf) {
                *(float2*)&Cf[(size_t)gr * ldc + gc]       = make_float2(v0, v1);
                *(float2*)&Cf[(size_t)(gr + 8) * ldc + gc] = make_float2(v2, v3);
            }
            if (Ch) {
                uint32_t hh, ll;
                pack_hl(v0, v1, hh, ll);
                *(uint32_t*)&Ch[(size_t)gr * ldc + gc] = hh;
                *(uint32_t*)&Cl[(size_t)gr * ldc + gc] = ll;
                pack_hl(v2, v3, hh, ll);
                *(uint32_t*)&Ch[(size_t)(gr + 8) * ldc + gc] = hh;
                *(uint32_t*)&Cl[(size_t)(gr + 8) * ldc + gc] = ll;
            }
        }
    }
}

// standalone GEMM (wo / ffn1 / ffn2)
__global__ __launch_bounds__(512, 1)
void gemm_bf3(int K,
              const __nv_bfloat16* __restrict__ Ah, const __nv_bfloat16* __restrict__ Al,
              const __nv_bfloat16* __restrict__ Bh, const __nv_bfloat16* __restrict__ Bl,
              const float* __restrict__ bias, float scale, int act,
              float* __restrict__ Cf,
              __nv_bfloat16* __restrict__ Ch, __nv_bfloat16* __restrict__ Cl,
              int ldc)
{
    extern __shared__ __align__(16) char smc[];
    gemm_core(smem_u32(smc), blockIdx.y * 256, blockIdx.x * 128, K,
              Ah, Al, Bh, Bl, bias, scale, act, Cf, Ch, Cl, ldc);
}

// fused Q-projection + merged K|V projection (independent GEMMs, one launch)
// blocks [0,256): Q (32 m-tiles x 8 n-tiles); [256,384): KV (8 x 16).
__global__ __launch_bounds__(512, 1)
void qkv_proj(const __nv_bfloat16* __restrict__ cAh, const __nv_bfloat16* __restrict__ cAl,
              const __nv_bfloat16* __restrict__ th,  const __nv_bfloat16* __restrict__ tl,
              const __nv_bfloat16* __restrict__ wih, const __nv_bfloat16* __restrict__ wil,
              const float* __restrict__ b_in,
              __nv_bfloat16* __restrict__ qh, __nv_bfloat16* __restrict__ ql,
              __nv_bfloat16* __restrict__ kvh, __nv_bfloat16* __restrict__ kvl)
{
    extern __shared__ __align__(16) char smc[];
    const uint32_t sb = smem_u32(smc);
    const int bx = blockIdx.x;
    if (bx < 256) {
        gemm_core(sb, (bx >> 3) * 256, (bx & 7) * 128, D_,
                  cAh, cAl, wih, wil, b_in, 0.125f, 0,
                  nullptr, qh, ql, D_);
    } else {
        const int i = bx - 256;
        gemm_core(sb, (i >> 4) * 256, (i & 15) * 128, D_,
                  th, tl, wih + (size_t)D_ * D_, wil + (size_t)D_ * D_,
                  b_in + D_, 1.f, 0, nullptr, kvh, kvl, LDKV_);
    }
}

// ---------------------------------------------------------------------------
// HMMA flash attention. Q fragments hoisted out of the s-chunk loop
// (32 regs; 1 CTA/SM so no occupancy cost). V row-major + ldmatrix.trans.
// ---------------------------------------------------------------------------
#define AQH 0
#define AQL 16384
#define AKH 32768
#define AKL 65536
#define AVH 98304
#define AVL 131072
#define ATT_DSMEM 163840

__global__ __launch_bounds__(256, 1)
void attn_tc(const __nv_bfloat16* __restrict__ qh, const __nv_bfloat16* __restrict__ ql,
             const __nv_bfloat16* __restrict__ kvh, const __nv_bfloat16* __restrict__ kvl,
             __nv_bfloat16* __restrict__ ch, __nv_bfloat16* __restrict__ cl)
{
    extern __shared__ __align__(16) char smc[];
    const uint32_t sb = smem_u32(smc);
    const int tid = threadIdx.x, lane = tid & 31, w = tid >> 5;
    const int bq = blockIdx.x * 128;
    const int h  = blockIdx.y, b = blockIdx.z;

    // ---- cp.async fills: Q[128x64], K[256x64], V[256x64] (all hi+lo) ------
    const size_t qbase = ((size_t)(b * LQ_ + bq)) * D_ + h * HD_;
    for (int e = tid; e < 1024; e += 256) {
        int r = e >> 3, c = e & 7;
        uint32_t off = r * 128 + ((c * 16) ^ ((r & 7) << 4));
        cp16(sb + AQH + off, qh + qbase + (size_t)r * D_ + c * 8);
        cp16(sb + AQL + off, ql + qbase + (size_t)r * D_ + c * 8);
    }
    const size_t kbase = ((size_t)(b * S_)) * LDKV_ + h * HD_;
    for (int e = tid; e < 2048; e += 256) {
        int r = e >> 3, c = e & 7;
        uint32_t off = r * 128 + ((c * 16) ^ ((r & 7) << 4));
        cp16(sb + AKH + off, kvh + kbase + (size_t)r * LDKV_ + c * 8);
        cp16(sb + AKL + off, kvl + kbase + (size_t)r * LDKV_ + c * 8);
    }
    for (int e = tid; e < 2048; e += 256) {     // V rows s (row-major [s][d])
        int r = e >> 3, c = e & 7;
        uint32_t off = r * 128 + ((c * 16) ^ ((r & 7) << 4));
        cp16(sb + AVH + off, kvh + kbase + (size_t)r * LDKV_ + 1024 + c * 8);
        cp16(sb + AVL + off, kvl + kbase + (size_t)r * LDKV_ + 1024 + c * 8);
    }
    CP_COMMIT();
    CP_WAIT0();
    __syncthreads();

    // ---- per-warp flash loop ---------------------------------------------
    const int qr = w * 16;
    const int rA = qr + (lane & 15);
    const int cadd = ((lane >> 4) & 1) * 16;

    // hoisted Q fragments (same frags previously reloaded each s-chunk)
    uint32_t qHf[4][4], qLf[4][4];
#pragma unroll
    for (int ks = 0; ks < 4; ks++) {
        uint32_t qoff = rA * 128 + ((ks * 32 + cadd) ^ ((rA & 7) << 4));
        ldsm_x4(qHf[ks], sb + AQH + qoff);
        ldsm_x4(qLf[ks], sb + AQL + qoff);
    }

    float O[8][4];
#pragma unroll
    for (int j = 0; j < 8; j++)
#pragma unroll
        for (int q = 0; q < 4; q++) O[j][q] = 0.f;
    float m0 = -1e30f, m1 = -1e30f, l0 = 0.f, l1 = 0.f;

    for (int t = 0; t < 4; ++t) {
        const int s0 = t * 64;
        float sc[8][4];
#pragma unroll
        for (int j = 0; j < 8; j++)
#pragma unroll
            for (int q = 0; q < 4; q++) sc[j][q] = 0.f;

        // scores = (Qh+Ql)(Kh+Kl)^T  (Q pre-scaled by 1/8)
#pragma unroll
        for (int ks = 0; ks < 4; ks++) {
#pragma unroll
            for (int p = 0; p < 4; p++) {
                int rB = s0 + p * 16 + (lane & 15);
                uint32_t boff = rB * 128 + ((ks * 32 + cadd) ^ ((rB & 7) << 4));
                uint32_t bh[4], bl[4];
                ldsm_x4(bh, sb + AKH + boff);
                ldsm_x4(bl, sb + AKL + boff);
                mma16816(sc[2*p],   qHf[ks], bh[0], bh[2]);
                mma16816(sc[2*p+1], qHf[ks], bh[1], bh[3]);
                mma16816(sc[2*p],   qHf[ks], bl[0], bl[2]);
                mma16816(sc[2*p+1], qHf[ks], bl[1], bl[3]);
                mma16816(sc[2*p],   qLf[ks], bh[0], bh[2]);
                mma16816(sc[2*p+1], qLf[ks], bh[1], bh[3]);
            }
        }

        // online softmax (rows r0 = lane>>2 and r0+8; quad = lanes xor 1,2)
        float mx0 = -1e30f, mx1 = -1e30f;
#pragma unroll
        for (int j = 0; j < 8; j++) {
            mx0 = fmaxf(mx0, fmaxf(sc[j][0], sc[j][1]));
            mx1 = fmaxf(mx1, fmaxf(sc[j][2], sc[j][3]));
        }
        mx0 = fmaxf(mx0, __shfl_xor_sync(0xffffffffu, mx0, 1));
        mx0 = fmaxf(mx0, __shfl_xor_sync(0xffffffffu, mx0, 2));
        mx1 = fmaxf(mx1, __shfl_xor_sync(0xffffffffu, mx1, 1));
        mx1 = fmaxf(mx1, __shfl_xor_sync(0xffffffffu, mx1, 2));
        float mn0 = fmaxf(m0, mx0), mn1 = fmaxf(m1, mx1);
        float a0 = __expf(m0 - mn0), a1 = __expf(m1 - mn1);
        m0 = mn0; m1 = mn1;
        float ls0 = 0.f, ls1 = 0.f;
#pragma unroll
        for (int j = 0; j < 8; j++) {
            sc[j][0] = __expf(sc[j][0] - m0);
            sc[j][1] = __expf(sc[j][1] - m0);
            sc[j][2] = __expf(sc[j][2] - m1);
            sc[j][3] = __expf(sc[j][3] - m1);
            ls0 += sc[j][0] + sc[j][1];
            ls1 += sc[j][2] + sc[j][3];
        }
        ls0 += __shfl_xor_sync(0xffffffffu, ls0, 1);
        ls0 += __shfl_xor_sync(0xffffffffu, ls0, 2);
        ls1 += __shfl_xor_sync(0xffffffffu, ls1, 1);
        ls1 += __shfl_xor_sync(0xffffffffu, ls1, 2);
        l0 = l0 * a0 + ls0;
        l1 = l1 * a1 + ls1;
#pragma unroll
        for (int j = 0; j < 8; j++) {
            O[j][0] *= a0; O[j][1] *= a0;
            O[j][2] *= a1; O[j][3] *= a1;
        }

        // PV: O += (Ph+Pl)(V) — B-frags via ldmatrix.trans on [s][d] rows.
#pragma unroll
        for (int g = 0; g < 4; g++) {
            uint32_t aPh[4], aPl[4];
            pack_hl(sc[2*g][0],   sc[2*g][1],   aPh[0], aPl[0]);
            pack_hl(sc[2*g][2],   sc[2*g][3],   aPh[1], aPl[1]);
            pack_hl(sc[2*g+1][0], sc[2*g+1][1], aPh[2], aPl[2]);
            pack_hl(sc[2*g+1][2], sc[2*g+1][3], aPh[3], aPl[3]);
            const int rV = s0 + g * 16 + (lane & 15);
#pragma unroll
            for (int pd = 0; pd < 4; pd++) {
                uint32_t voff = rV * 128 + ((pd * 32 + cadd) ^ ((rV & 7) << 4));
                uint32_t bh[4], bl[4];
                ldsm_x4_t(bh, sb + AVH + voff);
                ldsm_x4_t(bl, sb + AVL + voff);
                mma16816(O[2*pd],   aPh, bh[0], bh[1]);
                mma16816(O[2*pd+1], aPh, bh[2], bh[3]);
                mma16816(O[2*pd],   aPh, bl[0], bl[1]);
                mma16816(O[2*pd+1], aPh, bl[2], bl[3]);
                mma16816(O[2*pd],   aPl, bh[0], bh[1]);
                mma16816(O[2*pd+1], aPl, bh[2], bh[3]);
            }
        }
    }

    // ---- epilogue: O/l -> ctx bf16 hi/lo ---------------------------------
    const float i0 = 1.f / l0, i1 = 1.f / l1;
    const size_t gr0 = (size_t)(b * LQ_ + bq + qr + (lane >> 2));
    const size_t gr1 = gr0 + 8;
#pragma unroll
    for (int j = 0; j < 8; j++) {
        int gc = h * HD_ + j * 8 + (lane & 3) * 2;
        uint32_t hh, ll;
        pack_hl(O[j][0] * i0, O[j][1] * i0, hh, ll);
        *(uint32_t*)&ch[gr0 * D_ + gc] = hh;
        *(uint32_t*)&cl[gr0 * D_ + gc] = ll;
        pack_hl(O[j][2] * i1, O[j][3] * i1, hh, ll);
        *(uint32_t*)&ch[gr1 * D_ + gc] = hh;
        *(uint32_t*)&cl[gr1 * D_ + gc] = ll;
    }
}

// ---------------------------------------------------------------------------
// Epilogue: two layer-norms + sigmoid box (unchanged)
// ---------------------------------------------------------------------------
#define OUT_TGT 8388608u
#define OUT_BOX 16777216u

__global__ __launch_bounds__(256)
void ln_box_kernel(const float* __restrict__ ffn, const float* __restrict__ attn,
                   const float* __restrict__ g1, const float* __restrict__ be1,
                   const float* __restrict__ g2, const float* __restrict__ be2,
                   float* __restrict__ out)
{
    __shared__ float red[8];
    __shared__ float bcast;
    const int row = blockIdx.x;
    const int tid = threadIdx.x;
    const int lane = tid & 31, w = tid >> 5;

    float4 x = ((const float4*)(ffn + (size_t)row * D_))[tid];

    float s = x.x + x.y + x.z + x.w;
#pragma unroll
    for (int o = 16; o; o >>= 1) s += __shfl_xor_sync(0xffffffffu, s, o);
    if (lane == 0) red[w] = s;
    __syncthreads();
    if (w == 0) {
        float t = (lane < 8) ? red[lane] : 0.f;
#pragma unroll
        for (int o = 4; o; o >>= 1) t += __shfl_xor_sync(0xffffffffu, t, o);
        if (lane == 0) bcast = t * (1.f / 1024.f);
    }
    __syncthreads();
    const float mean = bcast;
    __syncthreads();

    float dx = x.x - mean, dy = x.y - mean, dz = x.z - mean, dw = x.w - mean;
    float sq = dx * dx + dy * dy + dz * dz + dw * dw;
#pragma unroll
    for (int o = 16; o; o >>= 1) sq += __shfl_xor_sync(0xffffffffu, sq, o);
    if (lane == 0) red[w] = sq;
    __syncthreads();
    if (w == 0) {
        float t = (lane < 8) ? red[lane] : 0.f;
#pragma unroll
        for (int o = 4; o; o >>= 1) t += __shfl_xor_sync(0xffffffffu, t, o);
        if (lane == 0) bcast = rsqrtf(t * (1.f / 1024.f) + 1e-5f);
    }
    __syncthreads();
    const float inv = bcast;

    float4 G1 = ((const float4*)g1)[tid];
    float4 B1 = ((const float4*)be1)[tid];
    float4 G2 = ((const float4*)g2)[tid];
    float4 B2 = ((const float4*)be2)[tid];

    float4 o1, o2;
    o1.x = dx * inv * G1.x + B1.x;  o2.x = dx * inv * G2.x + B2.x;
    o1.y = dy * inv * G1.y + B1.y;  o2.y = dy * inv * G2.y + B2.y;
    o1.z = dz * inv * G1.z + B1.z;  o2.z = dz * inv * G2.z + B2.z;
    o1.w = dw * inv * G1.w + B1.w;  o2.w = dw * inv * G2.w + B2.w;

    ((float4*)out)[(size_t)row * 256 + tid]             = o1;
    ((float4*)(out + OUT_TGT))[(size_t)row * 256 + tid] = o2;

    if (tid == 0) {
        const float* a = attn + (size_t)row * D_;
        float xc = 1.f / (1.f + __expf(-a[0]));
        float yc = 1.f / (1.f + __expf(-a[1]));
        float ww = 1.f / (1.f + __expf(-a[2]));
        float hh = 1.f / (1.f + __expf(-a[3]));
        float4 box = make_float4(xc - ww * 0.5f, yc - hh * 0.5f,
                                 xc + ww * 0.5f, yc + hh * 0.5f);
        *(float4*)(out + OUT_BOX + (size_t)row * 4) = box;
    }
}

// ---------------------------------------------------------------------------
// Launch
// ---------------------------------------------------------------------------
extern "C" void kernel_launch(void* const* d_in, const int* in_sizes, int n_in,
                              void* d_out, int out_size)
{
    const float* memory = (const float*)d_in[0];
    const float* gaze   = (const float*)d_in[1];
    const float* text   = (const float*)d_in[2];
    const float* w_in   = (const float*)d_in[3];
    const float* b_in   = (const float*)d_in[4];
    const float* w_o    = (const float*)d_in[5];
    const float* b_o    = (const float*)d_in[6];
    const float* w1     = (const float*)d_in[7];
    const float* b1     = (const float*)d_in[8];
    const float* w2     = (const float*)d_in[9];
    const float* b2     = (const float*)d_in[10];
    const float* g1     = (const float*)d_in[11];
    const float* be1    = (const float*)d_in[12];
    const float* g2     = (const float*)d_in[13];
    const float* be2    = (const float*)d_in[14];
    float* out = (float*)d_out;

    __nv_bfloat16 *cAh,*cAl,*th,*tl,*wih,*wil,*woh,*wol,*w1h,*w1l,*w2h,*w2l;
    __nv_bfloat16 *qh,*ql,*kvh,*kvl,*chb,*clb,*ah,*al,*mh,*ml;
    float *ATT,*FFN;
    cudaGetSymbolAddress((void**)&cAh, g_cAh); cudaGetSymbolAddress((void**)&cAl, g_cAl);
    cudaGetSymbolAddress((void**)&th,  g_th);  cudaGetSymbolAddress((void**)&tl,  g_tl);
    cudaGetSymbolAddress((void**)&wih, g_wih); cudaGetSymbolAddress((void**)&wil, g_wil);
    cudaGetSymbolAddress((void**)&woh, g_woh); cudaGetSymbolAddress((void**)&wol, g_wol);
    cudaGetSymbolAddress((void**)&w1h, g_w1h); cudaGetSymbolAddress((void**)&w1l, g_w1l);
    cudaGetSymbolAddress((void**)&w2h, g_w2h); cudaGetSymbolAddress((void**)&w2l, g_w2l);
    cudaGetSymbolAddress((void**)&qh,  g_qh);  cudaGetSymbolAddress((void**)&ql,  g_ql);
    cudaGetSymbolAddress((void**)&kvh, g_kvh); cudaGetSymbolAddress((void**)&kvl, g_kvl);
    cudaGetSymbolAddress((void**)&chb, g_ch);  cudaGetSymbolAddress((void**)&clb, g_cl);
    cudaGetSymbolAddress((void**)&ah,  g_ah);  cudaGetSymbolAddress((void**)&al,  g_al);
    cudaGetSymbolAddress((void**)&mh,  g_mh);  cudaGetSymbolAddress((void**)&ml,  g_ml);
    cudaGetSymbolAddress((void**)&ATT, g_att); cudaGetSymbolAddress((void**)&FFN, g_ffn);

    cudaFuncSetAttribute(gemm_bf3,
                         cudaFuncAttributeMaxDynamicSharedMemorySize, G_DSMEM);
    cudaFuncSetAttribute(qkv_proj,
                         cudaFuncAttributeMaxDynamicSharedMemorySize, G_DSMEM);
    cudaFuncSetAttribute(attn_tc,
                         cudaFuncAttributeMaxDynamicSharedMemorySize, ATT_DSMEM);

    dim3 blk(256), blk512(512);

    // ---- one fused input/weight split launch ----
    cvt_all<<<CVT_TOTAL / 256, blk>>>(memory, gaze, text, w_in, w_o, w1, w2,
                                      cAh, cAl, th, tl, wih, wil,
                                      woh, wol, w1h, w1l, w2h, w2l);

    // ---- fused Q + K|V projections (one launch, 384 CTAs) ----
    qkv_proj<<<384, blk512, G_DSMEM>>>(cAh, cAl, th, tl, wih, wil, b_in,
                                       qh, ql, kvh, kvl);

    // attention -> ctx bf16 hi/lo
    dim3 gA(LQ_ / 128, H_, B_);        // (8, 16, 8)
    attn_tc<<<gA, blk, ATT_DSMEM>>>(qh, ql, kvh, kvl, chb, clb);

    dim3 gQ(D_ / 128, MQ_ / 256);      // (8, 32)
    // output projection -> ATT fp32 + bf16
    gemm_bf3<<<gQ, blk512, G_DSMEM>>>(D_, chb, clb, woh, wol,
                                      b_o, 1.f, 0, ATT, ah, al, D_);
    // FFN1 (relu) -> bf16 only
    gemm_bf3<<<gQ, blk512, G_DSMEM>>>(D_, ah, al, w1h, w1l,
                                      b1, 1.f, 1, nullptr, mh, ml, D_);
    // FFN2 -> fp32 only
    gemm_bf3<<<gQ, blk512, G_DSMEM>>>(D_, mh, ml, w2h, w2l,
                                      b2, 1.f, 0, FFN, nullptr, nullptr, D_);

    // layer norms + box proposal
    ln_box_kernel<<<MQ_, blk>>>(FFN, ATT, g1, be1, g2, be2, out);
}